// round 4
// baseline (speedup 1.0000x reference)
#include <cuda_runtime.h>

// ---------------- problem constants ----------------
#define CB   8
#define CN   1024
#define CD   768
#define CH   12
#define CDKV 64
#define CDFF 3072
#define CE   16
#define CCAP 128
#define CBN  (CB*CN)          // 8192 tokens
#define CEC  (CE*CB*CCAP)     // 16384 expert slots

// ---------------- device scratch (no allocation allowed) ----------------
static __device__ float g_normed [CBN*CD];
static __device__ float g_q      [CBN*CD];
static __device__ float g_k      [CBN*CD];
static __device__ float g_v      [CBN*CD];
static __device__ float g_ao     [CBN*CD];   // attention out (pre-Wo)
static __device__ float g_h      [CBN*CD];   // residual 1
static __device__ float g_n2     [CBN*CD];   // normed2 (MoE input)
static __device__ float g_logits [CBN*CE];
static __device__ float g_raw    [CBN*CE];   // softmaxed gate probs
static __device__ int   g_e1[CBN], g_e2[CBN], g_s1[CBN], g_s2[CBN];
static __device__ float g_g1[CBN], g_g2[CBN];
static __device__ int   g_cnt1[CB*CE];       // pre-capacity top1 counts (density)
static __device__ int   g_route[CEC];        // global token index per slot, -1 empty
static __device__ float g_xin[CEC*CD];
static __device__ float g_mid[CEC*CDFF];     // 201 MB
static __device__ float g_xo [CEC*CD];

// ---------------- RMSNorm (T5, eps=1e-6) ----------------
__global__ void rmsnorm_kernel(const float* __restrict__ x,
                               const float* __restrict__ w,
                               float* __restrict__ y) {
    int row = blockIdx.x;
    const float* xr = x + (size_t)row * CD;
    float s = 0.f;
    for (int i = threadIdx.x; i < CD; i += 256) { float v = xr[i]; s = fmaf(v, v, s); }
    for (int o = 16; o; o >>= 1) s += __shfl_xor_sync(0xffffffffu, s, o);
    __shared__ float red[8];
    __shared__ float invs;
    if ((threadIdx.x & 31) == 0) red[threadIdx.x >> 5] = s;
    __syncthreads();
    if (threadIdx.x == 0) {
        float tot = 0.f;
        #pragma unroll
        for (int i = 0; i < 8; i++) tot += red[i];
        invs = rsqrtf(tot / CD + 1e-6f);
    }
    __syncthreads();
    float inv = invs;
    float* yr = y + (size_t)row * CD;
    for (int i = threadIdx.x; i < CD; i += 256) yr[i] = xr[i] * inv * w[i];
}

// ---------------- generic tiled GEMM: C = A[M,K] @ B[K,N] (+resid)(+relu) ----------------
// BM=BN=64, BK=16, 256 threads, 4x4 micro-tile per thread.
template<bool RELU, bool RESID>
__global__ void gemm_kernel(const float* __restrict__ A, const float* __restrict__ Bm,
                            const float* __restrict__ Rz, float* __restrict__ C,
                            int M, int Nn, int K,
                            long aS, long bS, long cS) {
    int z = blockIdx.z;
    A  += (long)z * aS;
    Bm += (long)z * bS;
    C  += (long)z * cS;
    __shared__ float As[16][68];   // padded: conflict-light STS, 16B-aligned rows
    __shared__ float Bs[16][64];
    int tid = threadIdx.x;
    int tx = tid & 15, ty = tid >> 4;
    int row0 = blockIdx.y * 64, col0 = blockIdx.x * 64;
    int aK = tid & 15;          // k within tile
    int aM = tid >> 4;          // row within tile (+16*i)
    int bN = tid & 63;
    int bK = tid >> 6;          // (+4*i)
    float c[4][4] = {};
    for (int k0 = 0; k0 < K; k0 += 16) {
        #pragma unroll
        for (int i = 0; i < 4; i++)
            As[aK][aM + 16*i] = A[(long)(row0 + aM + 16*i) * K + k0 + aK];
        #pragma unroll
        for (int i = 0; i < 4; i++)
            Bs[bK + 4*i][bN] = Bm[(long)(k0 + bK + 4*i) * Nn + col0 + bN];
        __syncthreads();
        #pragma unroll
        for (int kk = 0; kk < 16; kk++) {
            float a[4], b[4];
            #pragma unroll
            for (int i = 0; i < 4; i++) a[i] = As[kk][ty*4 + i];
            #pragma unroll
            for (int j = 0; j < 4; j++) b[j] = Bs[kk][tx*4 + j];
            #pragma unroll
            for (int i = 0; i < 4; i++)
                #pragma unroll
                for (int j = 0; j < 4; j++)
                    c[i][j] = fmaf(a[i], b[j], c[i][j]);
        }
        __syncthreads();
    }
    #pragma unroll
    for (int i = 0; i < 4; i++) {
        long r = row0 + ty*4 + i;
        long cc = col0 + tx*4;
        float4 v = make_float4(c[i][0], c[i][1], c[i][2], c[i][3]);
        if (RESID) {
            float4 rz = *(const float4*)(Rz + r * Nn + cc);
            v.x += rz.x; v.y += rz.y; v.z += rz.z; v.w += rz.w;
        }
        if (RELU) {
            v.x = fmaxf(v.x, 0.f); v.y = fmaxf(v.y, 0.f);
            v.z = fmaxf(v.z, 0.f); v.w = fmaxf(v.w, 0.f);
        }
        *(float4*)(C + r * Nn + cc) = v;
    }
}

// ---------------- flash attention (fp32, no scaling, additive mask bias) ----------------
// Mask is read as 32-bit words with a nonzero test: correct for both int32 (1)
// and float32 (0x3F800000) encodings of the boolean mask.
__global__ __launch_bounds__(128) void attn_kernel(const int* __restrict__ mask) {
    int bh = blockIdx.y;
    int b = bh / CH, h = bh % CH;
    int q = blockIdx.x * 128 + threadIdx.x;
    const float4* qp = (const float4*)(g_q + ((size_t)(b*CN + q)*CH + h) * CDKV);
    float4 qv[16], acc[16];
    #pragma unroll
    for (int i = 0; i < 16; i++) { qv[i] = qp[i]; acc[i] = make_float4(0,0,0,0); }
    float m = -1e30f, l = 0.f;
    __shared__ float4 Ks[32][16];
    __shared__ float4 Vs[32][16];
    __shared__ float  Sb[128][33];
    __shared__ float  Mb[32];
    for (int kt = 0; kt < CN; kt += 32) {
        #pragma unroll
        for (int i = 0; i < 4; i++) {
            int idx = threadIdx.x + i*128;
            int j = idx >> 4, d4 = idx & 15;
            size_t base = ((size_t)(b*CN + kt + j)*CH + h) * CDKV;
            Ks[j][d4] = *(const float4*)(g_k + base + d4*4);
            Vs[j][d4] = *(const float4*)(g_v + base + d4*4);
        }
        if (threadIdx.x < 32)
            Mb[threadIdx.x] = (mask[b*CN + kt + threadIdx.x] != 0) ? 0.f : -1e9f;
        __syncthreads();
        float tmax = -1e30f;
        #pragma unroll 4
        for (int j = 0; j < 32; j++) {
            float4 sv = make_float4(0,0,0,0);
            #pragma unroll
            for (int i = 0; i < 16; i++) {
                float4 k4 = Ks[j][i];
                sv.x = fmaf(qv[i].x, k4.x, sv.x);
                sv.y = fmaf(qv[i].y, k4.y, sv.y);
                sv.z = fmaf(qv[i].z, k4.z, sv.z);
                sv.w = fmaf(qv[i].w, k4.w, sv.w);
            }
            float s = (sv.x + sv.y) + (sv.z + sv.w) + Mb[j];
            Sb[threadIdx.x][j] = s;
            tmax = fmaxf(tmax, s);
        }
        float mn = fmaxf(m, tmax);
        float sc = __expf(m - mn);
        l *= sc;
        #pragma unroll
        for (int i = 0; i < 16; i++) {
            acc[i].x *= sc; acc[i].y *= sc; acc[i].z *= sc; acc[i].w *= sc;
        }
        #pragma unroll 4
        for (int j = 0; j < 32; j++) {
            float p = __expf(Sb[threadIdx.x][j] - mn);
            l += p;
            #pragma unroll
            for (int i = 0; i < 16; i++) {
                float4 v4 = Vs[j][i];
                acc[i].x = fmaf(p, v4.x, acc[i].x);
                acc[i].y = fmaf(p, v4.y, acc[i].y);
                acc[i].z = fmaf(p, v4.z, acc[i].z);
                acc[i].w = fmaf(p, v4.w, acc[i].w);
            }
        }
        m = mn;
        __syncthreads();
    }
    float inv = 1.f / l;
    float4* op = (float4*)(g_ao + ((size_t)(b*CN + q)*CH + h) * CDKV);
    #pragma unroll
    for (int i = 0; i < 16; i++)
        op[i] = make_float4(acc[i].x*inv, acc[i].y*inv, acc[i].z*inv, acc[i].w*inv);
}

// ---------------- gate logits: [8192,768] @ [768,16] ----------------
__global__ void logits_kernel(const float* __restrict__ gw) {
    int tid = threadIdx.x;
    int tok = blockIdx.x * 16 + (tid >> 4);
    int e = tid & 15;
    const float* xr = g_n2 + (size_t)tok * CD;
    float acc = 0.f;
    #pragma unroll 8
    for (int d = 0; d < CD; d++) acc = fmaf(xr[d], gw[d*CE + e], acc);
    g_logits[(size_t)tok*CE + e] = acc;
}

// ---------------- per-token gating: softmax + top2 ----------------
__global__ void gate_kernel() {
    int t = blockIdx.x * 256 + threadIdx.x;
    if (t >= CBN) return;
    float lg[CE];
    float mx = -1e30f;
    #pragma unroll
    for (int e = 0; e < CE; e++) { lg[e] = g_logits[(size_t)t*CE + e]; mx = fmaxf(mx, lg[e]); }
    float sum = 0.f;
    #pragma unroll
    for (int e = 0; e < CE; e++) { lg[e] = __expf(lg[e] - mx); sum += lg[e]; }
    float inv = 1.f / sum;
    #pragma unroll
    for (int e = 0; e < CE; e++) { lg[e] *= inv; g_raw[(size_t)t*CE + e] = lg[e]; }
    int i1 = 0; float b1 = lg[0];
    #pragma unroll
    for (int e = 1; e < CE; e++) if (lg[e] > b1) { b1 = lg[e]; i1 = e; }
    int i2 = -1; float b2 = -1.f;
    #pragma unroll
    for (int e = 0; e < CE; e++) if (e != i1 && lg[e] > b2) { b2 = lg[e]; i2 = e; }
    float denom = b1 + b2 + 1e-9f;
    g_e1[t] = i1; g_e2[t] = i2;
    g_g1[t] = b1 / denom; g_g2[t] = b2 / denom;
}

// ---------------- route init ----------------
__global__ void routeinit_kernel() {
    int i = blockIdx.x * 256 + threadIdx.x;
    if (i < CEC) g_route[i] = -1;
}

// ---------------- capacity assignment (sequential scan per (b,e)) ----------------
__global__ void capacity_kernel() {
    int b = blockIdx.x;
    int e = threadIdx.x;
    if (e >= CE) return;
    int cnt = 0;
    for (int n = 0; n < CN; n++) {
        int t = b*CN + n;
        if (g_e1[t] == e) {
            int pos = cnt++;
            if (pos < CCAP) {
                g_s1[t] = pos;
                g_route[(e*CB + b)*CCAP + pos] = t;
            } else {
                g_s1[t] = -1;
                g_g1[t] = 0.f;
            }
        }
    }
    g_cnt1[b*CE + e] = cnt;                  // pre-capacity count -> density
    int m1c = cnt < CCAP ? cnt : CCAP;       // post-capacity count -> slot offset
    int cnt2 = 0;
    for (int n = 0; n < CN; n++) {
        int t = b*CN + n;
        if (g_e2[t] == e) {
            int pos = cnt2++ + m1c;
            if (pos < CCAP) {
                g_s2[t] = pos;
                g_route[(e*CB + b)*CCAP + pos] = t;
            } else {
                g_s2[t] = -1;
                g_g2[t] = 0.f;
            }
        }
    }
}

// ---------------- gather tokens into expert slots ----------------
__global__ void gather_kernel() {
    int row = blockIdx.x;
    int t = g_route[row];
    float4* dst = (float4*)(g_xin + (size_t)row * CD);
    if (t < 0) {
        dst[threadIdx.x] = make_float4(0,0,0,0);
    } else {
        const float4* src = (const float4*)(g_n2 + (size_t)t * CD);
        dst[threadIdx.x] = src[threadIdx.x];
    }
}

// ---------------- weighted combine + residual 2 ----------------
__global__ void combine_kernel(float* __restrict__ out) {
    int t = blockIdx.x;
    int b = t / CN;
    const float4* hh = (const float4*)(g_h + (size_t)t * CD);
    float4 v = hh[threadIdx.x];
    int s1 = g_s1[t];
    if (s1 >= 0) {
        float gg = g_g1[t];
        const float4* x1 = (const float4*)(g_xo + ((size_t)(g_e1[t]*CB + b)*CCAP + s1) * CD);
        float4 a = x1[threadIdx.x];
        v.x = fmaf(gg, a.x, v.x); v.y = fmaf(gg, a.y, v.y);
        v.z = fmaf(gg, a.z, v.z); v.w = fmaf(gg, a.w, v.w);
    }
    int s2 = g_s2[t];
    if (s2 >= 0) {
        float gg = g_g2[t];
        const float4* x2 = (const float4*)(g_xo + ((size_t)(g_e2[t]*CB + b)*CCAP + s2) * CD);
        float4 a = x2[threadIdx.x];
        v.x = fmaf(gg, a.x, v.x); v.y = fmaf(gg, a.y, v.y);
        v.z = fmaf(gg, a.z, v.z); v.w = fmaf(gg, a.w, v.w);
    }
    ((float4*)out)[(size_t)t * (CD/4) + threadIdx.x] = v;
}

// ---------------- aux loss (deterministic reduction) ----------------
__global__ void loss_kernel(float* __restrict__ out, int out_size) {
    int tid = threadIdx.x;              // 128 threads = B*E
    int b = tid >> 4, e = tid & 15;
    float proxy = 0.f;
    for (int n = 0; n < CN; n++) proxy += g_raw[((size_t)(b*CN + n))*CE + e];
    proxy /= (float)CN;
    float dens = (float)g_cnt1[b*CE + e] / (float)CN;
    float v = proxy * dens;
    __shared__ float red[128];
    red[tid] = v;
    __syncthreads();
    for (int s = 64; s; s >>= 1) {
        if (tid < s) red[tid] += red[tid + s];
        __syncthreads();
    }
    if (tid == 0) {
        float loss = red[0] / (float)(CB*CE) * (float)(CE*CE) * 0.01f;
        const int base = CBN*CD;
        if (out_size > base) out[base] = loss;
        for (int i = base + 1; i < out_size; i++) out[i] = 0.f;
    }
}

// ---------------- launcher ----------------
extern "C" void kernel_launch(void* const* d_in, const int* in_sizes, int n_in,
                              void* d_out, int out_size) {
    const float* hid   = (const float*)d_in[0];
    const int*   mask  = (const int*)d_in[1];   // bool mask materialized as int32/float32; nonzero test
    const float* ln0   = (const float*)d_in[2];
    const float* Wq    = (const float*)d_in[3];
    const float* Wk    = (const float*)d_in[4];
    const float* Wv    = (const float*)d_in[5];
    const float* Wo    = (const float*)d_in[6];
    const float* ln1   = (const float*)d_in[7];
    const float* gw    = (const float*)d_in[8];
    const float* ew1   = (const float*)d_in[9];
    const float* ew2   = (const float*)d_in[10];
    float* out = (float*)d_out;

    float *p_normed, *p_q, *p_k, *p_v, *p_ao, *p_h, *p_n2, *p_xin, *p_mid, *p_xo;
    cudaGetSymbolAddress((void**)&p_normed, g_normed);
    cudaGetSymbolAddress((void**)&p_q,   g_q);
    cudaGetSymbolAddress((void**)&p_k,   g_k);
    cudaGetSymbolAddress((void**)&p_v,   g_v);
    cudaGetSymbolAddress((void**)&p_ao,  g_ao);
    cudaGetSymbolAddress((void**)&p_h,   g_h);
    cudaGetSymbolAddress((void**)&p_n2,  g_n2);
    cudaGetSymbolAddress((void**)&p_xin, g_xin);
    cudaGetSymbolAddress((void**)&p_mid, g_mid);
    cudaGetSymbolAddress((void**)&p_xo,  g_xo);

    // 1. RMSNorm 0
    rmsnorm_kernel<<<CBN, 256>>>(hid, ln0, p_normed);

    // 2. Q/K/V projections
    dim3 gproj(CD/64, CBN/64, 1);
    gemm_kernel<false,false><<<gproj, 256>>>(p_normed, Wq, nullptr, p_q, CBN, CD, CD, 0, 0, 0);
    gemm_kernel<false,false><<<gproj, 256>>>(p_normed, Wk, nullptr, p_k, CBN, CD, CD, 0, 0, 0);
    gemm_kernel<false,false><<<gproj, 256>>>(p_normed, Wv, nullptr, p_v, CBN, CD, CD, 0, 0, 0);

    // 3. attention
    attn_kernel<<<dim3(CN/128, CB*CH), 128>>>(mask);

    // 4. output projection + residual
    gemm_kernel<false,true><<<gproj, 256>>>(p_ao, Wo, hid, p_h, CBN, CD, CD, 0, 0, 0);

    // 5. RMSNorm 1
    rmsnorm_kernel<<<CBN, 256>>>(p_h, ln1, p_n2);

    // 6. gating
    logits_kernel<<<CBN/16, 256>>>(gw);
    gate_kernel<<<(CBN + 255)/256, 256>>>();
    routeinit_kernel<<<(CEC + 255)/256, 256>>>();
    capacity_kernel<<<CB, 32>>>();

    // 7. dispatch
    gather_kernel<<<CEC, CD/4>>>();

    // 8. expert FFN
    gemm_kernel<true,false><<<dim3(CDFF/64, (CB*CCAP)/64, CE), 256>>>(
        p_xin, ew1, nullptr, p_mid, CB*CCAP, CDFF, CD,
        (long)CB*CCAP*CD, (long)CD*CDFF, (long)CB*CCAP*CDFF);
    gemm_kernel<false,false><<<dim3(CD/64, (CB*CCAP)/64, CE), 256>>>(
        p_mid, ew2, nullptr, p_xo, CB*CCAP, CD, CDFF,
        (long)CB*CCAP*CDFF, (long)CDFF*CD, (long)CB*CCAP*CD);

    // 9. combine + residual 2
    combine_kernel<<<CBN, CD/4>>>(out);

    // 10. aux loss
    loss_kernel<<<1, 128>>>(out, out_size);
}

// round 7
// speedup vs baseline: 1.9987x; 1.9987x over previous
#include <cuda_runtime.h>
#include <cuda_bf16.h>
#include <cstdint>

// ---------------- problem constants ----------------
#define CB   8
#define CN   1024
#define CD   768
#define CH   12
#define CDKV 64
#define CDFF 3072
#define CE   16
#define CCAP 128
#define CBN  (CB*CN)          // 8192 tokens
#define CEC  (CE*CB*CCAP)     // 16384 expert slots
#define CMZ  (CB*CCAP)        // 1024 rows per expert

// ---------------- device scratch (no allocation allowed) ----------------
static __device__ float g_normed [CBN*CD];
static __device__ float g_q      [CBN*CD];
static __device__ float g_k      [CBN*CD];
static __device__ float g_v      [CBN*CD];
static __device__ float g_ao     [CBN*CD];
static __device__ float g_h      [CBN*CD];
static __device__ float g_n2     [CBN*CD];
static __device__ float g_logits [CBN*CE];
static __device__ float g_raw    [CBN*CE];
static __device__ int   g_e1[CBN], g_e2[CBN], g_s1[CBN], g_s2[CBN];
static __device__ float g_g1[CBN], g_g2[CBN];
static __device__ int   g_cnt1[CB*CE];
static __device__ int   g_route[CEC];
static __device__ float g_xo [CEC*CD];
// bf16 MoE path
static __device__ __nv_bfloat16 g_xinb[CEC*CD];        // dispatched tokens, bf16
static __device__ __nv_bfloat16 g_midb[CEC*CDFF];      // relu(ffn1), bf16
static __device__ __nv_bfloat16 g_w1t [CE*CDFF*CD];    // w1 transposed [e][DFF][D]
static __device__ __nv_bfloat16 g_w2t [CE*CD*CDFF];    // w2 transposed [e][D][DFF]

// ================= portable PTX helpers (sm_80+ features only) =================
__device__ __forceinline__ uint32_t smem_u32(const void* p) {
    uint32_t a;
    asm("{ .reg .u64 t; cvta.to.shared.u64 t, %1; cvt.u32.u64 %0, t; }" : "=r"(a) : "l"(p));
    return a;
}
#define CP16(dst, src) \
    asm volatile("cp.async.cg.shared.global [%0], [%1], 16;" :: "r"(dst), "l"(src) : "memory")
#define CPCOMMIT() asm volatile("cp.async.commit_group;" ::: "memory")
#define CPWAIT0()  asm volatile("cp.async.wait_group 0;" ::: "memory")
#define CPWAIT1()  asm volatile("cp.async.wait_group 1;" ::: "memory")
#define LDSM4(r0, r1, r2, r3, addr) \
    asm volatile("ldmatrix.sync.aligned.m8n8.x4.shared.b16 {%0,%1,%2,%3}, [%4];" \
        : "=r"(r0), "=r"(r1), "=r"(r2), "=r"(r3) : "r"(addr))
#define MMA16816(c, a, b0v, b1v) \
    asm volatile("mma.sync.aligned.m16n8k16.row.col.f32.bf16.bf16.f32 " \
        "{%0,%1,%2,%3}, {%4,%5,%6,%7}, {%8,%9}, {%0,%1,%2,%3};" \
        : "+f"((c)[0]), "+f"((c)[1]), "+f"((c)[2]), "+f"((c)[3]) \
        : "r"((a)[0]), "r"((a)[1]), "r"((a)[2]), "r"((a)[3]), "r"(b0v), "r"(b1v))

// ---------------- RMSNorm (T5, eps=1e-6) ----------------
__global__ void rmsnorm_kernel(const float* __restrict__ x,
                               const float* __restrict__ w,
                               float* __restrict__ y) {
    int row = blockIdx.x;
    const float* xr = x + (size_t)row * CD;
    float s = 0.f;
    for (int i = threadIdx.x; i < CD; i += 256) { float v = xr[i]; s = fmaf(v, v, s); }
    for (int o = 16; o; o >>= 1) s += __shfl_xor_sync(0xffffffffu, s, o);
    __shared__ float red[8];
    __shared__ float invs;
    if ((threadIdx.x & 31) == 0) red[threadIdx.x >> 5] = s;
    __syncthreads();
    if (threadIdx.x == 0) {
        float tot = 0.f;
        #pragma unroll
        for (int i = 0; i < 8; i++) tot += red[i];
        invs = rsqrtf(tot / CD + 1e-6f);
    }
    __syncthreads();
    float inv = invs;
    float* yr = y + (size_t)row * CD;
    for (int i = threadIdx.x; i < CD; i += 256) yr[i] = xr[i] * inv * w[i];
}

// ---------------- fp32 tiled GEMM (projections): C = A@B (+resid) ----------------
template<bool RELU, bool RESID>
__global__ void gemm_kernel(const float* __restrict__ A, const float* __restrict__ Bm,
                            const float* __restrict__ Rz, float* __restrict__ C,
                            int M, int Nn, int K,
                            long aS, long bS, long cS) {
    int z = blockIdx.z;
    A  += (long)z * aS;
    Bm += (long)z * bS;
    C  += (long)z * cS;
    __shared__ float As[16][68];
    __shared__ float Bs[16][64];
    int tid = threadIdx.x;
    int tx = tid & 15, ty = tid >> 4;
    int row0 = blockIdx.y * 64, col0 = blockIdx.x * 64;
    int aK = tid & 15;
    int aM = tid >> 4;
    int bN = tid & 63;
    int bK = tid >> 6;
    float c[4][4] = {};
    for (int k0 = 0; k0 < K; k0 += 16) {
        #pragma unroll
        for (int i = 0; i < 4; i++)
            As[aK][aM + 16*i] = A[(long)(row0 + aM + 16*i) * K + k0 + aK];
        #pragma unroll
        for (int i = 0; i < 4; i++)
            Bs[bK + 4*i][bN] = Bm[(long)(k0 + bK + 4*i) * Nn + col0 + bN];
        __syncthreads();
        #pragma unroll
        for (int kk = 0; kk < 16; kk++) {
            float a[4], b[4];
            #pragma unroll
            for (int i = 0; i < 4; i++) a[i] = As[kk][ty*4 + i];
            #pragma unroll
            for (int j = 0; j < 4; j++) b[j] = Bs[kk][tx*4 + j];
            #pragma unroll
            for (int i = 0; i < 4; i++)
                #pragma unroll
                for (int j = 0; j < 4; j++)
                    c[i][j] = fmaf(a[i], b[j], c[i][j]);
        }
        __syncthreads();
    }
    #pragma unroll
    for (int i = 0; i < 4; i++) {
        long r = row0 + ty*4 + i;
        long cc = col0 + tx*4;
        float4 v = make_float4(c[i][0], c[i][1], c[i][2], c[i][3]);
        if (RESID) {
            float4 rz = *(const float4*)(Rz + r * Nn + cc);
            v.x += rz.x; v.y += rz.y; v.z += rz.z; v.w += rz.w;
        }
        if (RELU) {
            v.x = fmaxf(v.x, 0.f); v.y = fmaxf(v.y, 0.f);
            v.z = fmaxf(v.z, 0.f); v.w = fmaxf(v.w, 0.f);
        }
        *(float4*)(C + r * Nn + cc) = v;
    }
}

// ---------------- flash attention (fp32) ----------------
__global__ __launch_bounds__(128) void attn_kernel(const int* __restrict__ mask) {
    int bh = blockIdx.y;
    int b = bh / CH, h = bh % CH;
    int q = blockIdx.x * 128 + threadIdx.x;
    const float4* qp = (const float4*)(g_q + ((size_t)(b*CN + q)*CH + h) * CDKV);
    float4 qv[16], acc[16];
    #pragma unroll
    for (int i = 0; i < 16; i++) { qv[i] = qp[i]; acc[i] = make_float4(0,0,0,0); }
    float m = -1e30f, l = 0.f;
    __shared__ float4 Ks[32][16];
    __shared__ float4 Vs[32][16];
    __shared__ float  Sb[128][33];
    __shared__ float  Mb[32];
    for (int kt = 0; kt < CN; kt += 32) {
        #pragma unroll
        for (int i = 0; i < 4; i++) {
            int idx = threadIdx.x + i*128;
            int j = idx >> 4, d4 = idx & 15;
            size_t base = ((size_t)(b*CN + kt + j)*CH + h) * CDKV;
            Ks[j][d4] = *(const float4*)(g_k + base + d4*4);
            Vs[j][d4] = *(const float4*)(g_v + base + d4*4);
        }
        if (threadIdx.x < 32)
            Mb[threadIdx.x] = (mask[b*CN + kt + threadIdx.x] != 0) ? 0.f : -1e9f;
        __syncthreads();
        float tmax = -1e30f;
        #pragma unroll 4
        for (int j = 0; j < 32; j++) {
            float4 sv = make_float4(0,0,0,0);
            #pragma unroll
            for (int i = 0; i < 16; i++) {
                float4 k4 = Ks[j][i];
                sv.x = fmaf(qv[i].x, k4.x, sv.x);
                sv.y = fmaf(qv[i].y, k4.y, sv.y);
                sv.z = fmaf(qv[i].z, k4.z, sv.z);
                sv.w = fmaf(qv[i].w, k4.w, sv.w);
            }
            float s = (sv.x + sv.y) + (sv.z + sv.w) + Mb[j];
            Sb[threadIdx.x][j] = s;
            tmax = fmaxf(tmax, s);
        }
        float mn = fmaxf(m, tmax);
        float sc = __expf(m - mn);
        l *= sc;
        #pragma unroll
        for (int i = 0; i < 16; i++) {
            acc[i].x *= sc; acc[i].y *= sc; acc[i].z *= sc; acc[i].w *= sc;
        }
        #pragma unroll 4
        for (int j = 0; j < 32; j++) {
            float p = __expf(Sb[threadIdx.x][j] - mn);
            l += p;
            #pragma unroll
            for (int i = 0; i < 16; i++) {
                float4 v4 = Vs[j][i];
                acc[i].x = fmaf(p, v4.x, acc[i].x);
                acc[i].y = fmaf(p, v4.y, acc[i].y);
                acc[i].z = fmaf(p, v4.z, acc[i].z);
                acc[i].w = fmaf(p, v4.w, acc[i].w);
            }
        }
        m = mn;
        __syncthreads();
    }
    float inv = 1.f / l;
    float4* op = (float4*)(g_ao + ((size_t)(b*CN + q)*CH + h) * CDKV);
    #pragma unroll
    for (int i = 0; i < 16; i++)
        op[i] = make_float4(acc[i].x*inv, acc[i].y*inv, acc[i].z*inv, acc[i].w*inv);
}

// ---------------- gate logits ----------------
__global__ void logits_kernel(const float* __restrict__ gw) {
    int tid = threadIdx.x;
    int tok = blockIdx.x * 16 + (tid >> 4);
    int e = tid & 15;
    const float* xr = g_n2 + (size_t)tok * CD;
    float acc = 0.f;
    #pragma unroll 8
    for (int d = 0; d < CD; d++) acc = fmaf(xr[d], gw[d*CE + e], acc);
    g_logits[(size_t)tok*CE + e] = acc;
}

// ---------------- gating: softmax + top2 ----------------
__global__ void gate_kernel() {
    int t = blockIdx.x * 256 + threadIdx.x;
    if (t >= CBN) return;
    float lg[CE];
    float mx = -1e30f;
    #pragma unroll
    for (int e = 0; e < CE; e++) { lg[e] = g_logits[(size_t)t*CE + e]; mx = fmaxf(mx, lg[e]); }
    float sum = 0.f;
    #pragma unroll
    for (int e = 0; e < CE; e++) { lg[e] = __expf(lg[e] - mx); sum += lg[e]; }
    float inv = 1.f / sum;
    #pragma unroll
    for (int e = 0; e < CE; e++) { lg[e] *= inv; g_raw[(size_t)t*CE + e] = lg[e]; }
    int i1 = 0; float b1 = lg[0];
    #pragma unroll
    for (int e = 1; e < CE; e++) if (lg[e] > b1) { b1 = lg[e]; i1 = e; }
    int i2 = -1; float b2 = -1.f;
    #pragma unroll
    for (int e = 0; e < CE; e++) if (e != i1 && lg[e] > b2) { b2 = lg[e]; i2 = e; }
    float denom = b1 + b2 + 1e-9f;
    g_e1[t] = i1; g_e2[t] = i2;
    g_g1[t] = b1 / denom; g_g2[t] = b2 / denom;
}

// ---------------- route init ----------------
__global__ void routeinit_kernel() {
    int i = blockIdx.x * 256 + threadIdx.x;
    if (i < CEC) g_route[i] = -1;
}

// ---------------- capacity assignment ----------------
__global__ void capacity_kernel() {
    int b = blockIdx.x;
    int e = threadIdx.x;
    if (e >= CE) return;
    int cnt = 0;
    for (int n = 0; n < CN; n++) {
        int t = b*CN + n;
        if (g_e1[t] == e) {
            int pos = cnt++;
            if (pos < CCAP) {
                g_s1[t] = pos;
                g_route[(e*CB + b)*CCAP + pos] = t;
            } else {
                g_s1[t] = -1;
                g_g1[t] = 0.f;
            }
        }
    }
    g_cnt1[b*CE + e] = cnt;
    int m1c = cnt < CCAP ? cnt : CCAP;
    int cnt2 = 0;
    for (int n = 0; n < CN; n++) {
        int t = b*CN + n;
        if (g_e2[t] == e) {
            int pos = cnt2++ + m1c;
            if (pos < CCAP) {
                g_s2[t] = pos;
                g_route[(e*CB + b)*CCAP + pos] = t;
            } else {
                g_s2[t] = -1;
                g_g2[t] = 0.f;
            }
        }
    }
}

// ---------------- gather tokens into expert slots (bf16 out) ----------------
__global__ void gather_bf16_kernel() {
    int row = blockIdx.x;
    int t = g_route[row];
    __nv_bfloat162* dst = (__nv_bfloat162*)(g_xinb + (size_t)row * CD);
    int i = threadIdx.x;  // 0..191 (float4 index)
    if (t < 0) {
        dst[2*i]   = __nv_bfloat162{__nv_bfloat16(0.f), __nv_bfloat16(0.f)};
        dst[2*i+1] = __nv_bfloat162{__nv_bfloat16(0.f), __nv_bfloat16(0.f)};
    } else {
        float4 v = ((const float4*)(g_n2 + (size_t)t * CD))[i];
        dst[2*i]   = __floats2bfloat162_rn(v.x, v.y);
        dst[2*i+1] = __floats2bfloat162_rn(v.z, v.w);
    }
}

// ---------------- weight transpose+convert: out[z][c][r] = bf16(in[z][r][c]) ----------------
__global__ void transpose_bf16_kernel(const float* __restrict__ in,
                                      __nv_bfloat16* __restrict__ out,
                                      int R, int Cc) {
    __shared__ float t[32][33];
    long zoff = (long)blockIdx.z * R * Cc;
    int r0 = blockIdx.y * 32, c0 = blockIdx.x * 32;
    int x = threadIdx.x, y = threadIdx.y;   // 32 x 8
    #pragma unroll
    for (int j = 0; j < 32; j += 8)
        t[y + j][x] = in[zoff + (long)(r0 + y + j) * Cc + c0 + x];
    __syncthreads();
    #pragma unroll
    for (int j = 0; j < 32; j += 8)
        out[zoff + (long)(c0 + y + j) * R + r0 + x] = __float2bfloat16(t[x][y + j]);
}

// ---------------- bf16 tensor-core GEMM via mma.sync (portable HMMA path) ----------------
// Per expert z: C[1024, Nn] = A[1024, K] @ B[Nn, K]^T, fp32 accum.
// 128x128 CTA tile, BK=32, 256 threads = 8 warps in a 4x2 grid (32x64 per warp).
// smem rows padded to LDS=40 bf16 (80B): conflict-free ldmatrix (20*r mod 32 distinct).
#define MMA_LDS   40
#define MMA_STAGE (128*MMA_LDS*2)   // bytes per stage

template<bool RELU, bool OUT_BF16>
__global__ __launch_bounds__(256) void moe_mma_gemm(
    const __nv_bfloat16* __restrict__ A,    // [z*1024][K] row-major
    const __nv_bfloat16* __restrict__ Bw,   // [z*Nn][K]  row-major (N-major weights)
    void* __restrict__ Cout,                // [z*1024][Nn]
    int Nn, int K)
{
    __shared__ __align__(16) __nv_bfloat16 sA[2][128*MMA_LDS];
    __shared__ __align__(16) __nv_bfloat16 sB[2][128*MMA_LDS];

    int e  = blockIdx.z;
    int m0 = blockIdx.y * 128;
    int n0 = blockIdx.x * 128;
    const __nv_bfloat16* Az = A  + ((long)e * 1024 + m0) * K;
    const __nv_bfloat16* Bz = Bw + ((long)e * Nn  + n0) * K;

    int tid = threadIdx.x, wid = tid >> 5, lane = tid & 31;
    int wm = wid & 3, wn = wid >> 2;              // 4x2 warp grid
    int warp_row = wm * 32, warp_col = wn * 64;

    // global->smem mapping: each thread copies two 16B chunks of one row
    int lrow = tid >> 1;                          // 0..127
    int lcol = (tid & 1) * 16;                    // bf16 col 0 or 16

    uint32_t sAb = smem_u32(sA), sBb = smem_u32(sB);
    uint32_t aoff = (uint32_t)(lrow * MMA_LDS + lcol) * 2;

    int nk = K >> 5;

    // prologue: load chunk 0 into stage 0
    {
        const __nv_bfloat16* ap = Az + (long)lrow * K + lcol;
        const __nv_bfloat16* bp = Bz + (long)lrow * K + lcol;
        CP16(sAb + aoff,      ap);
        CP16(sAb + aoff + 16, ap + 8);
        CP16(sBb + aoff,      bp);
        CP16(sBb + aoff + 16, bp + 8);
        CPCOMMIT();
    }

    float c[2][8][4];
    #pragma unroll
    for (int mi = 0; mi < 2; mi++)
        #pragma unroll
        for (int ni = 0; ni < 8; ni++)
            #pragma unroll
            for (int j = 0; j < 4; j++) c[mi][ni][j] = 0.f;

    // ldmatrix lane addressing (shared for A and B): row_in16 = lane&15, k half = (lane>>4)*8
    int lm_r = lane & 15;
    int lm_k = (lane >> 4) << 3;

    for (int kc = 0; kc < nk; kc++) {
        int s = kc & 1;
        if (kc + 1 < nk) {
            int s2 = s ^ 1;
            const __nv_bfloat16* ap = Az + (long)lrow * K + (kc+1)*32 + lcol;
            const __nv_bfloat16* bp = Bz + (long)lrow * K + (kc+1)*32 + lcol;
            CP16(sAb + s2*MMA_STAGE + aoff,      ap);
            CP16(sAb + s2*MMA_STAGE + aoff + 16, ap + 8);
            CP16(sBb + s2*MMA_STAGE + aoff,      bp);
            CP16(sBb + s2*MMA_STAGE + aoff + 16, bp + 8);
            CPCOMMIT();
            CPWAIT1();
        } else {
            CPWAIT0();
        }
        __syncthreads();

        uint32_t sAs = sAb + s*MMA_STAGE;
        uint32_t sBs = sBb + s*MMA_STAGE;
        #pragma unroll
        for (int k16 = 0; k16 < 32; k16 += 16) {
            uint32_t af[2][4];
            #pragma unroll
            for (int mi = 0; mi < 2; mi++) {
                int row = warp_row + mi*16 + lm_r;
                uint32_t ad = sAs + (uint32_t)(row * MMA_LDS + k16 + lm_k) * 2;
                LDSM4(af[mi][0], af[mi][1], af[mi][2], af[mi][3], ad);
            }
            uint32_t bf[4][4];
            #pragma unroll
            for (int nt = 0; nt < 4; nt++) {
                int nr = warp_col + nt*16 + lm_r;
                uint32_t bd = sBs + (uint32_t)(nr * MMA_LDS + k16 + lm_k) * 2;
                LDSM4(bf[nt][0], bf[nt][1], bf[nt][2], bf[nt][3], bd);
            }
            #pragma unroll
            for (int mi = 0; mi < 2; mi++)
                #pragma unroll
                for (int ni = 0; ni < 8; ni++) {
                    int g = ni >> 1, hh = ni & 1;
                    MMA16816(c[mi][ni], af[mi], bf[g][hh], bf[g][2 + hh]);
                }
        }
        __syncthreads();
    }

    // epilogue: thread (g = lane>>2, t = lane&3); c0,c1 -> (row g, cols 2t,2t+1); c2,c3 -> row g+8
    int eg = lane >> 2, et = lane & 3;
    #pragma unroll
    for (int mi = 0; mi < 2; mi++) {
        #pragma unroll
        for (int ni = 0; ni < 8; ni++) {
            long r  = m0 + warp_row + mi*16 + eg;
            long cc = n0 + warp_col + ni*8 + et*2;
            float v0 = c[mi][ni][0], v1 = c[mi][ni][1];
            float v2 = c[mi][ni][2], v3 = c[mi][ni][3];
            if (RELU) {
                v0 = fmaxf(v0, 0.f); v1 = fmaxf(v1, 0.f);
                v2 = fmaxf(v2, 0.f); v3 = fmaxf(v3, 0.f);
            }
            if (OUT_BF16) {
                __nv_bfloat16* Cb = (__nv_bfloat16*)Cout;
                *(__nv_bfloat162*)(Cb + ((long)e*1024 + r)     * Nn + cc) = __floats2bfloat162_rn(v0, v1);
                *(__nv_bfloat162*)(Cb + ((long)e*1024 + r + 8) * Nn + cc) = __floats2bfloat162_rn(v2, v3);
            } else {
                float* Cf = (float*)Cout;
                *(float2*)(Cf + ((long)e*1024 + r)     * Nn + cc) = make_float2(v0, v1);
                *(float2*)(Cf + ((long)e*1024 + r + 8) * Nn + cc) = make_float2(v2, v3);
            }
        }
    }
}

// ---------------- weighted combine + residual 2 ----------------
__global__ void combine_kernel(float* __restrict__ out) {
    int t = blockIdx.x;
    int b = t / CN;
    const float4* hh = (const float4*)(g_h + (size_t)t * CD);
    float4 v = hh[threadIdx.x];
    int s1 = g_s1[t];
    if (s1 >= 0) {
        float gg = g_g1[t];
        const float4* x1 = (const float4*)(g_xo + ((size_t)(g_e1[t]*CB + b)*CCAP + s1) * CD);
        float4 a = x1[threadIdx.x];
        v.x = fmaf(gg, a.x, v.x); v.y = fmaf(gg, a.y, v.y);
        v.z = fmaf(gg, a.z, v.z); v.w = fmaf(gg, a.w, v.w);
    }
    int s2 = g_s2[t];
    if (s2 >= 0) {
        float gg = g_g2[t];
        const float4* x2 = (const float4*)(g_xo + ((size_t)(g_e2[t]*CB + b)*CCAP + s2) * CD);
        float4 a = x2[threadIdx.x];
        v.x = fmaf(gg, a.x, v.x); v.y = fmaf(gg, a.y, v.y);
        v.z = fmaf(gg, a.z, v.z); v.w = fmaf(gg, a.w, v.w);
    }
    ((float4*)out)[(size_t)t * (CD/4) + threadIdx.x] = v;
}

// ---------------- aux loss ----------------
__global__ void loss_kernel(float* __restrict__ out, int out_size) {
    int tid = threadIdx.x;
    int b = tid >> 4, e = tid & 15;
    float proxy = 0.f;
    for (int n = 0; n < CN; n++) proxy += g_raw[((size_t)(b*CN + n))*CE + e];
    proxy /= (float)CN;
    float dens = (float)g_cnt1[b*CE + e] / (float)CN;
    float v = proxy * dens;
    __shared__ float red[128];
    red[tid] = v;
    __syncthreads();
    for (int s = 64; s; s >>= 1) {
        if (tid < s) red[tid] += red[tid + s];
        __syncthreads();
    }
    if (tid == 0) {
        float loss = red[0] / (float)(CB*CE) * (float)(CE*CE) * 0.01f;
        const int base = CBN*CD;
        if (out_size > base) out[base] = loss;
        for (int i = base + 1; i < out_size; i++) out[i] = 0.f;
    }
}

// ---------------- launcher ----------------
extern "C" void kernel_launch(void* const* d_in, const int* in_sizes, int n_in,
                              void* d_out, int out_size) {
    const float* hid   = (const float*)d_in[0];
    const int*   mask  = (const int*)d_in[1];
    const float* ln0   = (const float*)d_in[2];
    const float* Wq    = (const float*)d_in[3];
    const float* Wk    = (const float*)d_in[4];
    const float* Wv    = (const float*)d_in[5];
    const float* Wo    = (const float*)d_in[6];
    const float* ln1   = (const float*)d_in[7];
    const float* gw    = (const float*)d_in[8];
    const float* ew1   = (const float*)d_in[9];
    const float* ew2   = (const float*)d_in[10];
    float* out = (float*)d_out;

    float *p_normed, *p_q, *p_k, *p_v, *p_ao, *p_h, *p_n2, *p_xo;
    __nv_bfloat16 *p_xinb, *p_midb, *p_w1t, *p_w2t;
    cudaGetSymbolAddress((void**)&p_normed, g_normed);
    cudaGetSymbolAddress((void**)&p_q,    g_q);
    cudaGetSymbolAddress((void**)&p_k,    g_k);
    cudaGetSymbolAddress((void**)&p_v,    g_v);
    cudaGetSymbolAddress((void**)&p_ao,   g_ao);
    cudaGetSymbolAddress((void**)&p_h,    g_h);
    cudaGetSymbolAddress((void**)&p_n2,   g_n2);
    cudaGetSymbolAddress((void**)&p_xo,   g_xo);
    cudaGetSymbolAddress((void**)&p_xinb, g_xinb);
    cudaGetSymbolAddress((void**)&p_midb, g_midb);
    cudaGetSymbolAddress((void**)&p_w1t,  g_w1t);
    cudaGetSymbolAddress((void**)&p_w2t,  g_w2t);

    // weight transpose+convert (independent of activations; overlaps the front of the graph)
    transpose_bf16_kernel<<<dim3(CDFF/32, CD/32, CE), dim3(32,8)>>>(ew1, p_w1t, CD, CDFF);
    transpose_bf16_kernel<<<dim3(CD/32, CDFF/32, CE), dim3(32,8)>>>(ew2, p_w2t, CDFF, CD);

    // 1. RMSNorm 0
    rmsnorm_kernel<<<CBN, 256>>>(hid, ln0, p_normed);

    // 2. Q/K/V projections (fp32)
    dim3 gproj(CD/64, CBN/64, 1);
    gemm_kernel<false,false><<<gproj, 256>>>(p_normed, Wq, nullptr, p_q, CBN, CD, CD, 0, 0, 0);
    gemm_kernel<false,false><<<gproj, 256>>>(p_normed, Wk, nullptr, p_k, CBN, CD, CD, 0, 0, 0);
    gemm_kernel<false,false><<<gproj, 256>>>(p_normed, Wv, nullptr, p_v, CBN, CD, CD, 0, 0, 0);

    // 3. attention
    attn_kernel<<<dim3(CN/128, CB*CH), 128>>>(mask);

    // 4. output projection + residual
    gemm_kernel<false,true><<<gproj, 256>>>(p_ao, Wo, hid, p_h, CBN, CD, CD, 0, 0, 0);

    // 5. RMSNorm 1
    rmsnorm_kernel<<<CBN, 256>>>(p_h, ln1, p_n2);

    // 6. gating (fp32 -> routing bit-identical)
    logits_kernel<<<CBN/16, 256>>>(gw);
    gate_kernel<<<(CBN + 255)/256, 256>>>();
    routeinit_kernel<<<(CEC + 255)/256, 256>>>();
    capacity_kernel<<<CB, 32>>>();

    // 7. dispatch (bf16)
    gather_bf16_kernel<<<CEC, CD/4>>>();

    // 8. expert FFN on tensor cores (bf16 mma.sync, fp32 accum)
    moe_mma_gemm<true, true ><<<dim3(CDFF/128, CMZ/128, CE), 256>>>(p_xinb, p_w1t, p_midb, CDFF, CD);
    moe_mma_gemm<false,false><<<dim3(CD/128,   CMZ/128, CE), 256>>>(p_midb, p_w2t, p_xo,   CD,  CDFF);

    // 9. combine + residual 2
    combine_kernel<<<CBN, CD/4>>>(out);

    // 10. aux loss
    loss_kernel<<<1, 128>>>(out, out_size);
}

// round 8
// speedup vs baseline: 2.1360x; 1.0687x over previous
#include <cuda_runtime.h>
#include <cuda_fp16.h>
#include <cstdint>

// ---------------- problem constants ----------------
#define CB   8
#define CN   1024
#define CD   768
#define CH   12
#define CDKV 64
#define CDFF 3072
#define CE   16
#define CCAP 128
#define CBN  (CB*CN)          // 8192 tokens
#define CEC  (CE*CB*CCAP)     // 16384 expert slots
#define CMZ  (CB*CCAP)        // 1024 rows per expert
#define WSCALE 32.0f
#define WISCALE (1.0f/32.0f)

// ---------------- device scratch ----------------
static __device__ float g_q      [CBN*CD];
static __device__ float g_k      [CBN*CD];
static __device__ float g_v      [CBN*CD];
static __device__ float g_h      [CBN*CD];
static __device__ float g_n2     [CBN*CD];
static __device__ float g_logits [CBN*CE];
static __device__ float g_raw    [CBN*CE];
static __device__ int   g_e1[CBN], g_e2[CBN], g_s1[CBN], g_s2[CBN];
static __device__ float g_g1[CBN], g_g2[CBN];
static __device__ int   g_cnt1[CB*CE];
static __device__ int   g_route[CEC];
static __device__ float g_xo [CEC*CD];
// split-fp16 activations
static __device__ __half g_nh [CBN*CD], g_nl [CBN*CD];     // normed hi/lo
static __device__ __half g_aoh[CBN*CD], g_aol[CBN*CD];     // attn out hi/lo
// split-fp16 projection weights, transposed to [N][K], scaled by WSCALE
static __device__ __half g_wqh[CD*CD], g_wql[CD*CD];
static __device__ __half g_wkh[CD*CD], g_wkl[CD*CD];
static __device__ __half g_wvh[CD*CD], g_wvl[CD*CD];
static __device__ __half g_woh[CD*CD], g_wol[CD*CD];
// fp16 MoE path
static __device__ __half g_xinh[CEC*CD];
static __device__ __half g_midh[CEC*CDFF];
static __device__ __half g_w1t [CE*CDFF*CD];   // [e][DFF][D]
static __device__ __half g_w2t [CE*CD*CDFF];   // [e][D][DFF]

// ================= portable PTX helpers =================
__device__ __forceinline__ uint32_t smem_u32(const void* p) {
    uint32_t a;
    asm("{ .reg .u64 t; cvta.to.shared.u64 t, %1; cvt.u32.u64 %0, t; }" : "=r"(a) : "l"(p));
    return a;
}
#define CP16(dst, src) \
    asm volatile("cp.async.cg.shared.global [%0], [%1], 16;" :: "r"(dst), "l"(src) : "memory")
#define CPCOMMIT() asm volatile("cp.async.commit_group;" ::: "memory")
#define CPWAIT0()  asm volatile("cp.async.wait_group 0;" ::: "memory")
#define LDSM4(r0, r1, r2, r3, addr) \
    asm volatile("ldmatrix.sync.aligned.m8n8.x4.shared.b16 {%0,%1,%2,%3}, [%4];" \
        : "=r"(r0), "=r"(r1), "=r"(r2), "=r"(r3) : "r"(addr))
#define MMAH(c, a, b0v, b1v) \
    asm volatile("mma.sync.aligned.m16n8k16.row.col.f32.f16.f16.f32 " \
        "{%0,%1,%2,%3}, {%4,%5,%6,%7}, {%8,%9}, {%0,%1,%2,%3};" \
        : "+f"((c)[0]), "+f"((c)[1]), "+f"((c)[2]), "+f"((c)[3]) \
        : "r"((a)[0]), "r"((a)[1]), "r"((a)[2]), "r"((a)[3]), "r"(b0v), "r"(b1v))

// ---------------- RMSNorm (T5, eps=1e-6); OUTMODE 0=fp32, 1=split fp16 ----------------
template<int OUTMODE>
__global__ void rmsnorm_kernel(const float* __restrict__ x,
                               const float* __restrict__ w,
                               float* __restrict__ y,
                               __half* __restrict__ yh,
                               __half* __restrict__ yl) {
    int row = blockIdx.x;
    const float* xr = x + (size_t)row * CD;
    float s = 0.f;
    for (int i = threadIdx.x; i < CD; i += 256) { float v = xr[i]; s = fmaf(v, v, s); }
    for (int o = 16; o; o >>= 1) s += __shfl_xor_sync(0xffffffffu, s, o);
    __shared__ float red[8];
    __shared__ float invs;
    if ((threadIdx.x & 31) == 0) red[threadIdx.x >> 5] = s;
    __syncthreads();
    if (threadIdx.x == 0) {
        float tot = 0.f;
        #pragma unroll
        for (int i = 0; i < 8; i++) tot += red[i];
        invs = rsqrtf(tot / CD + 1e-6f);
    }
    __syncthreads();
    float inv = invs;
    for (int i = threadIdx.x; i < CD; i += 256) {
        float v = xr[i] * inv * w[i];
        if (OUTMODE == 0) {
            y[(size_t)row*CD + i] = v;
        } else {
            __half hv = __float2half_rn(v);
            yh[(size_t)row*CD + i] = hv;
            yl[(size_t)row*CD + i] = __float2half_rn(v - __half2float(hv));
        }
    }
}

// ---------------- unified fp16 tensor-core GEMM ----------------
// C[M,Nn](+z) = scale * (A[M,K] @ B[Nn,K]^T) (+Rz) (+relu), fp32 accum.
// TERMS=1: single product (Ahi,Bhi). TERMS=3: split hi/lo, products hh+hl+lh.
// 128x128 CTA tile, 256 threads (8 warps, 4x2, 32x64 each), 2-stage cp.async,
// one __syncthreads per k-chunk.
template<int TERMS, bool RELU, bool RESID, bool OUTH>
__global__ __launch_bounds__(256) void mma_gemm(
    const __half* __restrict__ Ahi, const __half* __restrict__ Alo,
    const __half* __restrict__ Bhi, const __half* __restrict__ Blo,
    const float* __restrict__ Rz, void* __restrict__ Cout,
    int Nn, int K, float scale, long zA, long zB, long zC)
{
    constexpr int BK   = (TERMS == 3) ? 16 : 32;
    constexpr int LDSs = BK + 8;                 // 24 or 40 halves: LDSM-conflict-free
    constexpr int NT   = (TERMS == 3) ? 4 : 2;   // tiles: Ahi[,Alo],Bhi[,Blo]
    constexpr int CPR  = BK / 8;                 // cp16 chunks per row
    constexpr uint32_t TILEB  = 128u * LDSs * 2; // bytes per tile
    constexpr uint32_t STAGEB = NT * TILEB;
    __shared__ __align__(16) __half sm[2][NT][128 * LDSs];

    long e = blockIdx.z;
    int m0 = blockIdx.y * 128, n0 = blockIdx.x * 128;
    const __half* base[NT];
    base[0] = Ahi + e*zA + (long)m0 * K;
    if (TERMS == 3) {
        base[1] = Alo + e*zA + (long)m0 * K;
        base[2] = Bhi + e*zB + (long)n0 * K;
        base[3] = Blo + e*zB + (long)n0 * K;
    } else {
        base[1] = Bhi + e*zB + (long)n0 * K;
    }

    int tid = threadIdx.x, lane = tid & 31, wid = tid >> 5;
    int warp_row = (wid & 3) * 32, warp_col = (wid >> 2) * 64;
    uint32_t sb = smem_u32(sm);

    // per-thread loader coords: 4 cp.async chunks of 16B
    int rws[4], cls[4], tls[4];
    #pragma unroll
    for (int j = 0; j < 4; j++) {
        int c = tid * 4 + j;
        int row = c / CPR;
        cls[j] = (c % CPR) * 8;
        tls[j] = row >> 7;
        rws[j] = row & 127;
    }

    int nk = K / BK;
    // prologue: stage 0
    #pragma unroll
    for (int j = 0; j < 4; j++) {
        uint32_t dst = sb + tls[j]*TILEB + (uint32_t)(rws[j]*LDSs + cls[j]) * 2;
        CP16(dst, base[tls[j]] + (long)rws[j]*K + cls[j]);
    }
    CPCOMMIT();

    float acc[2][8][4];
    #pragma unroll
    for (int mi = 0; mi < 2; mi++)
        #pragma unroll
        for (int ni = 0; ni < 8; ni++)
            #pragma unroll
            for (int j = 0; j < 4; j++) acc[mi][ni][j] = 0.f;

    int lm_r = lane & 15, lm_k = (lane >> 4) << 3;

    for (int kc = 0; kc < nk; kc++) {
        CPWAIT0();
        __syncthreads();   // data visible + all warps done with other buffer
        if (kc + 1 < nk) {
            uint32_t s2 = (uint32_t)((kc + 1) & 1) * STAGEB;
            int k0 = (kc + 1) * BK;
            #pragma unroll
            for (int j = 0; j < 4; j++) {
                uint32_t dst = sb + s2 + tls[j]*TILEB + (uint32_t)(rws[j]*LDSs + cls[j]) * 2;
                CP16(dst, base[tls[j]] + (long)rws[j]*K + k0 + cls[j]);
            }
            CPCOMMIT();
        }
        uint32_t st = sb + (uint32_t)(kc & 1) * STAGEB;
        #pragma unroll
        for (int k16 = 0; k16 < BK; k16 += 16) {
            uint32_t afh[2][4], afl[2][4];
            #pragma unroll
            for (int mi = 0; mi < 2; mi++) {
                int row = warp_row + mi*16 + lm_r;
                LDSM4(afh[mi][0], afh[mi][1], afh[mi][2], afh[mi][3],
                      st + (uint32_t)(row*LDSs + k16 + lm_k) * 2);
                if (TERMS == 3)
                    LDSM4(afl[mi][0], afl[mi][1], afl[mi][2], afl[mi][3],
                          st + TILEB + (uint32_t)(row*LDSs + k16 + lm_k) * 2);
            }
            constexpr uint32_t BHOFF = (TERMS == 3) ? 2u*TILEB : 1u*TILEB;
            #pragma unroll
            for (int nt = 0; nt < 4; nt++) {
                int nr = warp_col + nt*16 + lm_r;
                uint32_t bh[4], bl[4];
                LDSM4(bh[0], bh[1], bh[2], bh[3],
                      st + BHOFF + (uint32_t)(nr*LDSs + k16 + lm_k) * 2);
                if (TERMS == 3)
                    LDSM4(bl[0], bl[1], bl[2], bl[3],
                          st + 3u*TILEB + (uint32_t)(nr*LDSs + k16 + lm_k) * 2);
                #pragma unroll
                for (int mi = 0; mi < 2; mi++)
                    #pragma unroll
                    for (int hh = 0; hh < 2; hh++) {
                        float* cc = acc[mi][nt*2 + hh];
                        MMAH(cc, afh[mi], bh[hh], bh[2 + hh]);
                        if (TERMS == 3) {
                            MMAH(cc, afh[mi], bl[hh], bl[2 + hh]);
                            MMAH(cc, afl[mi], bh[hh], bh[2 + hh]);
                        }
                    }
            }
        }
    }

    // epilogue
    int eg = lane >> 2, et = lane & 3;
    #pragma unroll
    for (int mi = 0; mi < 2; mi++) {
        #pragma unroll
        for (int ni = 0; ni < 8; ni++) {
            long r  = m0 + warp_row + mi*16 + eg;
            long cc = n0 + warp_col + ni*8 + et*2;
            float v0 = acc[mi][ni][0]*scale, v1 = acc[mi][ni][1]*scale;
            float v2 = acc[mi][ni][2]*scale, v3 = acc[mi][ni][3]*scale;
            if (RESID) {
                float2 r0 = *(const float2*)(Rz + r*Nn + cc);
                float2 r1 = *(const float2*)(Rz + (r+8)*Nn + cc);
                v0 += r0.x; v1 += r0.y; v2 += r1.x; v3 += r1.y;
            }
            if (RELU) {
                v0 = fmaxf(v0, 0.f); v1 = fmaxf(v1, 0.f);
                v2 = fmaxf(v2, 0.f); v3 = fmaxf(v3, 0.f);
            }
            if (OUTH) {
                __half* C = (__half*)Cout + e*zC;
                *(__half2*)(C + r*Nn + cc)     = __floats2half2_rn(v0, v1);
                *(__half2*)(C + (r+8)*Nn + cc) = __floats2half2_rn(v2, v3);
            } else {
                float* C = (float*)Cout + e*zC;
                *(float2*)(C + r*Nn + cc)     = make_float2(v0, v1);
                *(float2*)(C + (r+8)*Nn + cc) = make_float2(v2, v3);
            }
        }
    }
}

// ---------------- flash attention (fp32 compute; split-fp16 output) ----------------
__global__ __launch_bounds__(128) void attn_kernel(const int* __restrict__ mask) {
    int bh = blockIdx.y;
    int b = bh / CH, h = bh % CH;
    int q = blockIdx.x * 128 + threadIdx.x;
    const float4* qp = (const float4*)(g_q + ((size_t)(b*CN + q)*CH + h) * CDKV);
    float4 qv[16], acc[16];
    #pragma unroll
    for (int i = 0; i < 16; i++) { qv[i] = qp[i]; acc[i] = make_float4(0,0,0,0); }
    float m = -1e30f, l = 0.f;
    __shared__ float4 Ks[32][16];
    __shared__ float4 Vs[32][16];
    __shared__ float  Sb[128][33];
    __shared__ float  Mb[32];
    for (int kt = 0; kt < CN; kt += 32) {
        #pragma unroll
        for (int i = 0; i < 4; i++) {
            int idx = threadIdx.x + i*128;
            int j = idx >> 4, d4 = idx & 15;
            size_t base = ((size_t)(b*CN + kt + j)*CH + h) * CDKV;
            Ks[j][d4] = *(const float4*)(g_k + base + d4*4);
            Vs[j][d4] = *(const float4*)(g_v + base + d4*4);
        }
        if (threadIdx.x < 32)
            Mb[threadIdx.x] = (mask[b*CN + kt + threadIdx.x] != 0) ? 0.f : -1e9f;
        __syncthreads();
        float tmax = -1e30f;
        #pragma unroll 4
        for (int j = 0; j < 32; j++) {
            float4 sv = make_float4(0,0,0,0);
            #pragma unroll
            for (int i = 0; i < 16; i++) {
                float4 k4 = Ks[j][i];
                sv.x = fmaf(qv[i].x, k4.x, sv.x);
                sv.y = fmaf(qv[i].y, k4.y, sv.y);
                sv.z = fmaf(qv[i].z, k4.z, sv.z);
                sv.w = fmaf(qv[i].w, k4.w, sv.w);
            }
            float s = (sv.x + sv.y) + (sv.z + sv.w) + Mb[j];
            Sb[threadIdx.x][j] = s;
            tmax = fmaxf(tmax, s);
        }
        float mn = fmaxf(m, tmax);
        float sc = __expf(m - mn);
        l *= sc;
        #pragma unroll
        for (int i = 0; i < 16; i++) {
            acc[i].x *= sc; acc[i].y *= sc; acc[i].z *= sc; acc[i].w *= sc;
        }
        #pragma unroll 4
        for (int j = 0; j < 32; j++) {
            float p = __expf(Sb[threadIdx.x][j] - mn);
            l += p;
            #pragma unroll
            for (int i = 0; i < 16; i++) {
                float4 v4 = Vs[j][i];
                acc[i].x = fmaf(p, v4.x, acc[i].x);
                acc[i].y = fmaf(p, v4.y, acc[i].y);
                acc[i].z = fmaf(p, v4.z, acc[i].z);
                acc[i].w = fmaf(p, v4.w, acc[i].w);
            }
        }
        m = mn;
        __syncthreads();
    }
    float inv = 1.f / l;
    size_t ob = ((size_t)(b*CN + q)*CH + h) * CDKV;
    #pragma unroll
    for (int i = 0; i < 16; i++) {
        float o[4] = {acc[i].x*inv, acc[i].y*inv, acc[i].z*inv, acc[i].w*inv};
        #pragma unroll
        for (int c = 0; c < 4; c++) {
            __half hv = __float2half_rn(o[c]);
            g_aoh[ob + i*4 + c] = hv;
            g_aol[ob + i*4 + c] = __float2half_rn(o[c] - __half2float(hv));
        }
    }
}

// ---------------- gate logits (fp32: routing exactness) ----------------
__global__ void logits_kernel(const float* __restrict__ gw) {
    int tid = threadIdx.x;
    int tok = blockIdx.x * 16 + (tid >> 4);
    int e = tid & 15;
    const float* xr = g_n2 + (size_t)tok * CD;
    float acc = 0.f;
    #pragma unroll 8
    for (int d = 0; d < CD; d++) acc = fmaf(xr[d], gw[d*CE + e], acc);
    g_logits[(size_t)tok*CE + e] = acc;
}

// ---------------- gating: softmax + top2 ----------------
__global__ void gate_kernel() {
    int t = blockIdx.x * 256 + threadIdx.x;
    if (t >= CBN) return;
    float lg[CE];
    float mx = -1e30f;
    #pragma unroll
    for (int e = 0; e < CE; e++) { lg[e] = g_logits[(size_t)t*CE + e]; mx = fmaxf(mx, lg[e]); }
    float sum = 0.f;
    #pragma unroll
    for (int e = 0; e < CE; e++) { lg[e] = __expf(lg[e] - mx); sum += lg[e]; }
    float inv = 1.f / sum;
    #pragma unroll
    for (int e = 0; e < CE; e++) { lg[e] *= inv; g_raw[(size_t)t*CE + e] = lg[e]; }
    int i1 = 0; float b1 = lg[0];
    #pragma unroll
    for (int e = 1; e < CE; e++) if (lg[e] > b1) { b1 = lg[e]; i1 = e; }
    int i2 = -1; float b2 = -1.f;
    #pragma unroll
    for (int e = 0; e < CE; e++) if (e != i1 && lg[e] > b2) { b2 = lg[e]; i2 = e; }
    float denom = b1 + b2 + 1e-9f;
    g_e1[t] = i1; g_e2[t] = i2;
    g_g1[t] = b1 / denom; g_g2[t] = b2 / denom;
}

// ---------------- route init ----------------
__global__ void routeinit_kernel() {
    int i = blockIdx.x * 256 + threadIdx.x;
    if (i < CEC) g_route[i] = -1;
}

// ---------------- capacity assignment (sequential per (b,e)) ----------------
__global__ void capacity_kernel() {
    int b = blockIdx.x;
    int e = threadIdx.x;
    if (e >= CE) return;
    int cnt = 0;
    for (int n = 0; n < CN; n++) {
        int t = b*CN + n;
        if (g_e1[t] == e) {
            int pos = cnt++;
            if (pos < CCAP) {
                g_s1[t] = pos;
                g_route[(e*CB + b)*CCAP + pos] = t;
            } else {
                g_s1[t] = -1;
                g_g1[t] = 0.f;
            }
        }
    }
    g_cnt1[b*CE + e] = cnt;
    int m1c = cnt < CCAP ? cnt : CCAP;
    int cnt2 = 0;
    for (int n = 0; n < CN; n++) {
        int t = b*CN + n;
        if (g_e2[t] == e) {
            int pos = cnt2++ + m1c;
            if (pos < CCAP) {
                g_s2[t] = pos;
                g_route[(e*CB + b)*CCAP + pos] = t;
            } else {
                g_s2[t] = -1;
                g_g2[t] = 0.f;
            }
        }
    }
}

// ---------------- gather tokens into expert slots (fp16 out) ----------------
__global__ void gather_h_kernel() {
    int row = blockIdx.x;
    int t = g_route[row];
    __half2* dst = (__half2*)(g_xinh + (size_t)row * CD);
    int i = threadIdx.x;  // 0..191
    if (t < 0) {
        __half2 z = __floats2half2_rn(0.f, 0.f);
        dst[2*i] = z; dst[2*i+1] = z;
    } else {
        float4 v = ((const float4*)(g_n2 + (size_t)t * CD))[i];
        dst[2*i]   = __floats2half2_rn(v.x, v.y);
        dst[2*i+1] = __floats2half2_rn(v.z, v.w);
    }
}

// ---------------- weight transpose(+split): out[z][c][r] = half(in[z][r][c]*scale) ----------------
template<bool SPLIT>
__global__ void transpose_split_kernel(const float* __restrict__ in,
                                       __half* __restrict__ hi,
                                       __half* __restrict__ lo,
                                       int R, int Cc, float scale) {
    __shared__ float t[32][33];
    long zoff = (long)blockIdx.z * R * Cc;
    int r0 = blockIdx.y * 32, c0 = blockIdx.x * 32;
    int x = threadIdx.x, y = threadIdx.y;   // 32 x 8
    #pragma unroll
    for (int j = 0; j < 32; j += 8)
        t[y + j][x] = in[zoff + (long)(r0 + y + j) * Cc + c0 + x];
    __syncthreads();
    #pragma unroll
    for (int j = 0; j < 32; j += 8) {
        float v = t[x][y + j] * scale;
        __half hv = __float2half_rn(v);
        long o = zoff + (long)(c0 + y + j) * R + r0 + x;
        hi[o] = hv;
        if (SPLIT) lo[o] = __float2half_rn(v - __half2float(hv));
    }
}

// ---------------- weighted combine + residual 2 ----------------
__global__ void combine_kernel(float* __restrict__ out) {
    int t = blockIdx.x;
    int b = t / CN;
    const float4* hh = (const float4*)(g_h + (size_t)t * CD);
    float4 v = hh[threadIdx.x];
    int s1 = g_s1[t];
    if (s1 >= 0) {
        float gg = g_g1[t];
        const float4* x1 = (const float4*)(g_xo + ((size_t)(g_e1[t]*CB + b)*CCAP + s1) * CD);
        float4 a = x1[threadIdx.x];
        v.x = fmaf(gg, a.x, v.x); v.y = fmaf(gg, a.y, v.y);
        v.z = fmaf(gg, a.z, v.z); v.w = fmaf(gg, a.w, v.w);
    }
    int s2 = g_s2[t];
    if (s2 >= 0) {
        float gg = g_g2[t];
        const float4* x2 = (const float4*)(g_xo + ((size_t)(g_e2[t]*CB + b)*CCAP + s2) * CD);
        float4 a = x2[threadIdx.x];
        v.x = fmaf(gg, a.x, v.x); v.y = fmaf(gg, a.y, v.y);
        v.z = fmaf(gg, a.z, v.z); v.w = fmaf(gg, a.w, v.w);
    }
    ((float4*)out)[(size_t)t * (CD/4) + threadIdx.x] = v;
}

// ---------------- aux loss ----------------
__global__ void loss_kernel(float* __restrict__ out, int out_size) {
    int tid = threadIdx.x;
    int b = tid >> 4, e = tid & 15;
    float proxy = 0.f;
    for (int n = 0; n < CN; n++) proxy += g_raw[((size_t)(b*CN + n))*CE + e];
    proxy /= (float)CN;
    float dens = (float)g_cnt1[b*CE + e] / (float)CN;
    float v = proxy * dens;
    __shared__ float red[128];
    red[tid] = v;
    __syncthreads();
    for (int s = 64; s; s >>= 1) {
        if (tid < s) red[tid] += red[tid + s];
        __syncthreads();
    }
    if (tid == 0) {
        float loss = red[0] / (float)(CB*CE) * (float)(CE*CE) * 0.01f;
        const int base = CBN*CD;
        if (out_size > base) out[base] = loss;
        for (int i = base + 1; i < out_size; i++) out[i] = 0.f;
    }
}

// ---------------- launcher ----------------
extern "C" void kernel_launch(void* const* d_in, const int* in_sizes, int n_in,
                              void* d_out, int out_size) {
    const float* hid   = (const float*)d_in[0];
    const int*   mask  = (const int*)d_in[1];
    const float* ln0   = (const float*)d_in[2];
    const float* Wq    = (const float*)d_in[3];
    const float* Wk    = (const float*)d_in[4];
    const float* Wv    = (const float*)d_in[5];
    const float* Wo    = (const float*)d_in[6];
    const float* ln1   = (const float*)d_in[7];
    const float* gw    = (const float*)d_in[8];
    const float* ew1   = (const float*)d_in[9];
    const float* ew2   = (const float*)d_in[10];
    float* out = (float*)d_out;

    float *p_q, *p_k, *p_v, *p_h, *p_n2, *p_xo;
    __half *p_nh, *p_nl, *p_aoh, *p_aol;
    __half *p_wqh, *p_wql, *p_wkh, *p_wkl, *p_wvh, *p_wvl, *p_woh, *p_wol;
    __half *p_xinh, *p_midh, *p_w1t, *p_w2t;
    cudaGetSymbolAddress((void**)&p_q,    g_q);
    cudaGetSymbolAddress((void**)&p_k,    g_k);
    cudaGetSymbolAddress((void**)&p_v,    g_v);
    cudaGetSymbolAddress((void**)&p_h,    g_h);
    cudaGetSymbolAddress((void**)&p_n2,   g_n2);
    cudaGetSymbolAddress((void**)&p_xo,   g_xo);
    cudaGetSymbolAddress((void**)&p_nh,   g_nh);
    cudaGetSymbolAddress((void**)&p_nl,   g_nl);
    cudaGetSymbolAddress((void**)&p_aoh,  g_aoh);
    cudaGetSymbolAddress((void**)&p_aol,  g_aol);
    cudaGetSymbolAddress((void**)&p_wqh,  g_wqh);
    cudaGetSymbolAddress((void**)&p_wql,  g_wql);
    cudaGetSymbolAddress((void**)&p_wkh,  g_wkh);
    cudaGetSymbolAddress((void**)&p_wkl,  g_wkl);
    cudaGetSymbolAddress((void**)&p_wvh,  g_wvh);
    cudaGetSymbolAddress((void**)&p_wvl,  g_wvl);
    cudaGetSymbolAddress((void**)&p_woh,  g_woh);
    cudaGetSymbolAddress((void**)&p_wol,  g_wol);
    cudaGetSymbolAddress((void**)&p_xinh, g_xinh);
    cudaGetSymbolAddress((void**)&p_midh, g_midh);
    cudaGetSymbolAddress((void**)&p_w1t,  g_w1t);
    cudaGetSymbolAddress((void**)&p_w2t,  g_w2t);

    // ---- weight prep (independent of activations) ----
    dim3 tsb(32, 8);
    transpose_split_kernel<true><<<dim3(CD/32, CD/32, 1), tsb>>>(Wq, p_wqh, p_wql, CD, CD, WSCALE);
    transpose_split_kernel<true><<<dim3(CD/32, CD/32, 1), tsb>>>(Wk, p_wkh, p_wkl, CD, CD, WSCALE);
    transpose_split_kernel<true><<<dim3(CD/32, CD/32, 1), tsb>>>(Wv, p_wvh, p_wvl, CD, CD, WSCALE);
    transpose_split_kernel<true><<<dim3(CD/32, CD/32, 1), tsb>>>(Wo, p_woh, p_wol, CD, CD, WSCALE);
    transpose_split_kernel<false><<<dim3(CDFF/32, CD/32, CE), tsb>>>(ew1, p_w1t, nullptr, CD, CDFF, 1.0f);
    transpose_split_kernel<false><<<dim3(CD/32, CDFF/32, CE), tsb>>>(ew2, p_w2t, nullptr, CDFF, CD, 1.0f);

    // 1. RMSNorm 0 -> split fp16
    rmsnorm_kernel<1><<<CBN, 256>>>(hid, ln0, nullptr, p_nh, p_nl);

    // 2. Q/K/V projections: split-fp16 3-term tensor GEMM, fp32 out
    dim3 gproj(CD/128, CBN/128, 1);
    mma_gemm<3,false,false,false><<<gproj, 256>>>(p_nh, p_nl, p_wqh, p_wql, nullptr, p_q, CD, CD, WISCALE, 0, 0, 0);
    mma_gemm<3,false,false,false><<<gproj, 256>>>(p_nh, p_nl, p_wkh, p_wkl, nullptr, p_k, CD, CD, WISCALE, 0, 0, 0);
    mma_gemm<3,false,false,false><<<gproj, 256>>>(p_nh, p_nl, p_wvh, p_wvl, nullptr, p_v, CD, CD, WISCALE, 0, 0, 0);

    // 3. attention (fp32), writes split-fp16 ao
    attn_kernel<<<dim3(CN/128, CB*CH), 128>>>(mask);

    // 4. output projection + residual -> h (fp32)
    mma_gemm<3,false,true,false><<<gproj, 256>>>(p_aoh, p_aol, p_woh, p_wol, hid, p_h, CD, CD, WISCALE, 0, 0, 0);

    // 5. RMSNorm 1 -> fp32 (gating + gather input)
    rmsnorm_kernel<0><<<CBN, 256>>>(p_h, ln1, p_n2, nullptr, nullptr);

    // 6. gating (fp32: routing bit-exact)
    logits_kernel<<<CBN/16, 256>>>(gw);
    gate_kernel<<<(CBN + 255)/256, 256>>>();
    routeinit_kernel<<<(CEC + 255)/256, 256>>>();
    capacity_kernel<<<CB, 32>>>();

    // 7. dispatch (fp16)
    gather_h_kernel<<<CEC, CD/4>>>();

    // 8. expert FFN (fp16 mma, fp32 accum)
    mma_gemm<1,true,false,true ><<<dim3(CDFF/128, CMZ/128, CE), 256>>>(
        p_xinh, nullptr, p_w1t, nullptr, nullptr, p_midh, CDFF, CD, 1.0f,
        (long)CMZ*CD, (long)CDFF*CD, (long)CMZ*CDFF);
    mma_gemm<1,false,false,false><<<dim3(CD/128, CMZ/128, CE), 256>>>(
        p_midh, nullptr, p_w2t, nullptr, nullptr, p_xo, CD, CDFF, 1.0f,
        (long)CMZ*CDFF, (long)CD*CDFF, (long)CMZ*CD);

    // 9. combine + residual 2
    combine_kernel<<<CBN, CD/4>>>(out);

    // 10. aux loss
    loss_kernel<<<1, 128>>>(out, out_size);
}

// round 10
// speedup vs baseline: 2.6609x; 1.2458x over previous
#include <cuda_runtime.h>
#include <cuda_fp16.h>
#include <cstdint>

// ---------------- problem constants ----------------
#define CB   8
#define CN   1024
#define CD   768
#define CH   12
#define CDKV 64
#define CDFF 3072
#define CE   16
#define CCAP 128
#define CBN  (CB*CN)          // 8192 tokens
#define CEC  (CE*CB*CCAP)     // 16384 expert slots
#define CMZ  (CB*CCAP)        // 1024 rows per expert
#define WSCALE 32.0f
#define WISCALE (1.0f/32.0f)

// ---------------- device scratch ----------------
static __device__ float g_q      [CBN*CD];
static __device__ float g_k      [CBN*CD];
static __device__ float g_v      [CBN*CD];
static __device__ float g_h      [CBN*CD];
static __device__ float g_n2     [CBN*CD];
static __device__ float g_logits [CBN*CE];
static __device__ float g_raw    [CBN*CE];
static __device__ int   g_e1[CBN], g_e2[CBN], g_s1[CBN], g_s2[CBN];
static __device__ float g_g1[CBN], g_g2[CBN];
static __device__ int   g_cnt1[CB*CE];
static __device__ int   g_route[CEC];
static __device__ float g_xo [CEC*CD];
// split-fp16 activations
static __device__ __half g_nh [CBN*CD], g_nl [CBN*CD];     // normed hi/lo
static __device__ __half g_aoh[CBN*CD], g_aol[CBN*CD];     // attn out hi/lo
// fp16 projection weights, native [K][N] layout, scaled by WSCALE, split hi/lo
static __device__ __half g_wqh[CD*CD], g_wql[CD*CD];
static __device__ __half g_wkh[CD*CD], g_wkl[CD*CD];
static __device__ __half g_wvh[CD*CD], g_wvl[CD*CD];
static __device__ __half g_woh[CD*CD], g_wol[CD*CD];
// fp16 MoE path (weights stay native [K][N]; no transpose)
static __device__ __half g_xinh[CEC*CD];
static __device__ __half g_midh[CEC*CDFF];
static __device__ __half g_w1h [CE*CD*CDFF];   // [e][D][DFF]
static __device__ __half g_w2h [CE*CDFF*CD];   // [e][DFF][D]

// ================= portable PTX helpers =================
__device__ __forceinline__ uint32_t smem_u32(const void* p) {
    uint32_t a;
    asm("{ .reg .u64 t; cvta.to.shared.u64 t, %1; cvt.u32.u64 %0, t; }" : "=r"(a) : "l"(p));
    return a;
}
#define CP16(dst, src) \
    asm volatile("cp.async.cg.shared.global [%0], [%1], 16;" :: "r"(dst), "l"(src) : "memory")
#define CPCOMMIT() asm volatile("cp.async.commit_group;" ::: "memory")
#define CPWAIT0()  asm volatile("cp.async.wait_group 0;" ::: "memory")
#define LDSM4(r0, r1, r2, r3, addr) \
    asm volatile("ldmatrix.sync.aligned.m8n8.x4.shared.b16 {%0,%1,%2,%3}, [%4];" \
        : "=r"(r0), "=r"(r1), "=r"(r2), "=r"(r3) : "r"(addr))
#define LDSM4T(r0, r1, r2, r3, addr) \
    asm volatile("ldmatrix.sync.aligned.m8n8.x4.trans.shared.b16 {%0,%1,%2,%3}, [%4];" \
        : "=r"(r0), "=r"(r1), "=r"(r2), "=r"(r3) : "r"(addr))
#define MMAH(c, a, b0v, b1v) \
    asm volatile("mma.sync.aligned.m16n8k16.row.col.f32.f16.f16.f32 " \
        "{%0,%1,%2,%3}, {%4,%5,%6,%7}, {%8,%9}, {%0,%1,%2,%3};" \
        : "+f"((c)[0]), "+f"((c)[1]), "+f"((c)[2]), "+f"((c)[3]) \
        : "r"((a)[0]), "r"((a)[1]), "r"((a)[2]), "r"((a)[3]), "r"(b0v), "r"(b1v))

// ---------------- RMSNorm (T5, eps=1e-6); OUTMODE 0=fp32, 1=split fp16 ----------------
template<int OUTMODE>
__global__ void rmsnorm_kernel(const float* __restrict__ x,
                               const float* __restrict__ w,
                               float* __restrict__ y,
                               __half* __restrict__ yh,
                               __half* __restrict__ yl) {
    int row = blockIdx.x;
    const float* xr = x + (size_t)row * CD;
    float s = 0.f;
    for (int i = threadIdx.x; i < CD; i += 256) { float v = xr[i]; s = fmaf(v, v, s); }
    for (int o = 16; o; o >>= 1) s += __shfl_xor_sync(0xffffffffu, s, o);
    __shared__ float red[8];
    __shared__ float invs;
    if ((threadIdx.x & 31) == 0) red[threadIdx.x >> 5] = s;
    __syncthreads();
    if (threadIdx.x == 0) {
        float tot = 0.f;
        #pragma unroll
        for (int i = 0; i < 8; i++) tot += red[i];
        invs = rsqrtf(tot / CD + 1e-6f);
    }
    __syncthreads();
    float inv = invs;
    for (int i = threadIdx.x; i < CD; i += 256) {
        float v = xr[i] * inv * w[i];
        if (OUTMODE == 0) {
            y[(size_t)row*CD + i] = v;
        } else {
            __half hv = __float2half_rn(v);
            yh[(size_t)row*CD + i] = hv;
            yl[(size_t)row*CD + i] = __float2half_rn(v - __half2float(hv));
        }
    }
}

// ---------------- unified fp16 tensor-core GEMM (B consumed via ldmatrix.trans) ----------------
// C[M,Nn](+z) = scale * (A[M,K] @ B[K,Nn]) (+Rz) (+relu), fp32 accum.
// A row-major [M][K]; B row-major [K][Nn] (native weight layout — NO pre-transpose).
// TERMS=1: single product. TERMS=3: split hi/lo, hh + hl + lh.
// 128x128 CTA tile, 256 threads (8 warps, 4x2, 32x64 each), 2-stage cp.async.
template<int TERMS, bool RELU, bool RESID, bool OUTH>
__global__ __launch_bounds__(256) void mma_gemm(
    const __half* __restrict__ Ahi, const __half* __restrict__ Alo,
    const __half* __restrict__ Bhi, const __half* __restrict__ Blo,
    const float* __restrict__ Rz, void* __restrict__ Cout,
    int Nn, int K, float scale, long zA, long zB, long zC)
{
    constexpr int BK    = (TERMS == 3) ? 16 : 32;
    constexpr int NA    = (TERMS == 3) ? 2 : 1;       // A tiles (hi[,lo]); B tiles same count
    constexpr int LDSA  = BK + 8;                      // halves
    constexpr int LDSB  = 136;                         // halves (128 + 8 pad)
    constexpr uint32_t ATILEB = 128u * LDSA * 2;
    constexpr uint32_t BTILEB = (uint32_t)BK * LDSB * 2;
    constexpr uint32_t STAGEB = NA * (ATILEB + BTILEB);
    constexpr int ACH = 128 * (BK / 8);                // 16B chunks per A tile
    constexpr int BCH = BK * 16;                       // 16B chunks per B tile
    constexpr int CPT = NA * (ACH + BCH) / 256;        // chunks per thread (=4)
    __shared__ __align__(16) unsigned char sm[2 * STAGEB];

    long e = blockIdx.z;
    int m0 = blockIdx.y * 128, n0 = blockIdx.x * 128;

    int tid = threadIdx.x, lane = tid & 31, wid = tid >> 5;
    int warp_row = (wid & 3) * 32, warp_col = (wid >> 2) * 64;
    uint32_t sb = smem_u32(sm);

    // per-thread loader slots
    const __half* cur[CPT];
    long gstep[CPT];
    uint32_t sd[CPT];
    #pragma unroll
    for (int j = 0; j < CPT; j++) {
        int c = tid + j * 256;
        if (c < NA * ACH) {
            int tile = c / ACH;
            int rr = (c % ACH) / (BK / 8);
            int c8 = c % (BK / 8);
            sd[j] = tile * (ATILEB + BTILEB) + (uint32_t)(rr * LDSA + c8 * 8) * 2;
            const __half* src = (tile == 0 ? Ahi : Alo);
            cur[j] = src + e * zA + (long)(m0 + rr) * K + c8 * 8;
            gstep[j] = BK;
        } else {
            int c2 = c - NA * ACH;
            int tile = c2 / BCH;
            int rr = (c2 % BCH) / 16;        // k row within tile
            int c8 = c2 % 16;                // 16B chunk within 256B row
            sd[j] = tile * (ATILEB + BTILEB) + ATILEB + (uint32_t)(rr * LDSB + c8 * 8) * 2;
            const __half* src = (tile == 0 ? Bhi : Blo);
            cur[j] = src + e * zB + (long)rr * Nn + n0 + c8 * 8;
            gstep[j] = (long)BK * Nn;
        }
    }

    int nk = K / BK;
    // prologue: stage 0
    #pragma unroll
    for (int j = 0; j < CPT; j++) {
        CP16(sb + sd[j], cur[j]);
        cur[j] += gstep[j];
    }
    CPCOMMIT();

    float acc[2][8][4];
    #pragma unroll
    for (int mi = 0; mi < 2; mi++)
        #pragma unroll
        for (int ni = 0; ni < 8; ni++)
            #pragma unroll
            for (int j = 0; j < 4; j++) acc[mi][ni][j] = 0.f;

    int lm_r = lane & 15, lm_k = (lane >> 4) << 3;

    for (int kc = 0; kc < nk; kc++) {
        CPWAIT0();
        __syncthreads();
        if (kc + 1 < nk) {
            uint32_t s2 = (uint32_t)((kc + 1) & 1) * STAGEB;
            #pragma unroll
            for (int j = 0; j < CPT; j++) {
                CP16(sb + s2 + sd[j], cur[j]);
                cur[j] += gstep[j];
            }
            CPCOMMIT();
        }
        uint32_t st = sb + (uint32_t)(kc & 1) * STAGEB;
        #pragma unroll
        for (int k16 = 0; k16 < BK; k16 += 16) {
            // A fragments (non-trans; rows m, k-major)
            uint32_t afh[2][4], afl[2][4];
            #pragma unroll
            for (int mi = 0; mi < 2; mi++) {
                int row = warp_row + mi*16 + lm_r;
                LDSM4(afh[mi][0], afh[mi][1], afh[mi][2], afh[mi][3],
                      st + (uint32_t)(row*LDSA + k16 + lm_k) * 2);
                if (TERMS == 3)
                    LDSM4(afl[mi][0], afl[mi][1], afl[mi][2], afl[mi][3],
                          st + (ATILEB + BTILEB) + (uint32_t)(row*LDSA + k16 + lm_k) * 2);
            }
            // B fragments via ldmatrix.trans from [BK][128] k-major tiles.
            // groups: t0-7 k0-7/n, t8-15 k8-15/n, t16-31 same at n+8.
            // pairs: cols n..n+7 -> {r0,r1}; n+8..n+15 -> {r2,r3}.
            #pragma unroll
            for (int nt = 0; nt < 4; nt++) {
                uint32_t boff = (uint32_t)((k16 + lm_r) * LDSB + warp_col + nt*16 + lm_k) * 2;
                uint32_t bh[4], bl[4];
                LDSM4T(bh[0], bh[1], bh[2], bh[3], st + ATILEB + boff);
                if (TERMS == 3)
                    LDSM4T(bl[0], bl[1], bl[2], bl[3],
                           st + (ATILEB + BTILEB) + ATILEB + boff);
                #pragma unroll
                for (int mi = 0; mi < 2; mi++)
                    #pragma unroll
                    for (int hh = 0; hh < 2; hh++) {
                        float* cc = acc[mi][nt*2 + hh];
                        MMAH(cc, afh[mi], bh[2*hh], bh[2*hh + 1]);
                        if (TERMS == 3) {
                            MMAH(cc, afh[mi], bl[2*hh], bl[2*hh + 1]);
                            MMAH(cc, afl[mi], bh[2*hh], bh[2*hh + 1]);
                        }
                    }
            }
        }
    }

    // epilogue
    int eg = lane >> 2, et = lane & 3;
    #pragma unroll
    for (int mi = 0; mi < 2; mi++) {
        #pragma unroll
        for (int ni = 0; ni < 8; ni++) {
            long r  = m0 + warp_row + mi*16 + eg;
            long cc = n0 + warp_col + ni*8 + et*2;
            float v0 = acc[mi][ni][0]*scale, v1 = acc[mi][ni][1]*scale;
            float v2 = acc[mi][ni][2]*scale, v3 = acc[mi][ni][3]*scale;
            if (RESID) {
                float2 r0 = *(const float2*)(Rz + r*Nn + cc);
                float2 r1 = *(const float2*)(Rz + (r+8)*Nn + cc);
                v0 += r0.x; v1 += r0.y; v2 += r1.x; v3 += r1.y;
            }
            if (RELU) {
                v0 = fmaxf(v0, 0.f); v1 = fmaxf(v1, 0.f);
                v2 = fmaxf(v2, 0.f); v3 = fmaxf(v3, 0.f);
            }
            if (OUTH) {
                __half* C = (__half*)Cout + e*zC;
                *(__half2*)(C + r*Nn + cc)     = __floats2half2_rn(v0, v1);
                *(__half2*)(C + (r+8)*Nn + cc) = __floats2half2_rn(v2, v3);
            } else {
                float* C = (float*)Cout + e*zC;
                *(float2*)(C + r*Nn + cc)     = make_float2(v0, v1);
                *(float2*)(C + (r+8)*Nn + cc) = make_float2(v2, v3);
            }
        }
    }
}

// ---------------- flash attention (fp32 compute; split-fp16 output) ----------------
__global__ __launch_bounds__(128) void attn_kernel(const int* __restrict__ mask) {
    int bh = blockIdx.y;
    int b = bh / CH, h = bh % CH;
    int q = blockIdx.x * 128 + threadIdx.x;
    const float4* qp = (const float4*)(g_q + ((size_t)(b*CN + q)*CH + h) * CDKV);
    float4 qv[16], acc[16];
    #pragma unroll
    for (int i = 0; i < 16; i++) { qv[i] = qp[i]; acc[i] = make_float4(0,0,0,0); }
    float m = -1e30f, l = 0.f;
    __shared__ float4 Ks[32][16];
    __shared__ float4 Vs[32][16];
    __shared__ float  Sb[128][33];
    __shared__ float  Mb[32];
    for (int kt = 0; kt < CN; kt += 32) {
        #pragma unroll
        for (int i = 0; i < 4; i++) {
            int idx = threadIdx.x + i*128;
            int j = idx >> 4, d4 = idx & 15;
            size_t base = ((size_t)(b*CN + kt + j)*CH + h) * CDKV;
            Ks[j][d4] = *(const float4*)(g_k + base + d4*4);
            Vs[j][d4] = *(const float4*)(g_v + base + d4*4);
        }
        if (threadIdx.x < 32)
            Mb[threadIdx.x] = (mask[b*CN + kt + threadIdx.x] != 0) ? 0.f : -1e9f;
        __syncthreads();
        float tmax = -1e30f;
        #pragma unroll 4
        for (int j = 0; j < 32; j++) {
            float4 sv = make_float4(0,0,0,0);
            #pragma unroll
            for (int i = 0; i < 16; i++) {
                float4 k4 = Ks[j][i];
                sv.x = fmaf(qv[i].x, k4.x, sv.x);
                sv.y = fmaf(qv[i].y, k4.y, sv.y);
                sv.z = fmaf(qv[i].z, k4.z, sv.z);
                sv.w = fmaf(qv[i].w, k4.w, sv.w);
            }
            float s = (sv.x + sv.y) + (sv.z + sv.w) + Mb[j];
            Sb[threadIdx.x][j] = s;
            tmax = fmaxf(tmax, s);
        }
        float mn = fmaxf(m, tmax);
        float sc = __expf(m - mn);
        l *= sc;
        #pragma unroll
        for (int i = 0; i < 16; i++) {
            acc[i].x *= sc; acc[i].y *= sc; acc[i].z *= sc; acc[i].w *= sc;
        }
        #pragma unroll 4
        for (int j = 0; j < 32; j++) {
            float p = __expf(Sb[threadIdx.x][j] - mn);
            l += p;
            #pragma unroll
            for (int i = 0; i < 16; i++) {
                float4 v4 = Vs[j][i];
                acc[i].x = fmaf(p, v4.x, acc[i].x);
                acc[i].y = fmaf(p, v4.y, acc[i].y);
                acc[i].z = fmaf(p, v4.z, acc[i].z);
                acc[i].w = fmaf(p, v4.w, acc[i].w);
            }
        }
        m = mn;
        __syncthreads();
    }
    float inv = 1.f / l;
    size_t ob = ((size_t)(b*CN + q)*CH + h) * CDKV;
    #pragma unroll
    for (int i = 0; i < 16; i++) {
        float o[4] = {acc[i].x*inv, acc[i].y*inv, acc[i].z*inv, acc[i].w*inv};
        #pragma unroll
        for (int c = 0; c < 4; c++) {
            __half hv = __float2half_rn(o[c]);
            g_aoh[ob + i*4 + c] = hv;
            g_aol[ob + i*4 + c] = __float2half_rn(o[c] - __half2float(hv));
        }
    }
}

// ---------------- gate logits (fp32: routing exactness) ----------------
__global__ void logits_kernel(const float* __restrict__ gw) {
    int tid = threadIdx.x;
    int tok = blockIdx.x * 16 + (tid >> 4);
    int e = tid & 15;
    const float* xr = g_n2 + (size_t)tok * CD;
    float acc = 0.f;
    #pragma unroll 8
    for (int d = 0; d < CD; d++) acc = fmaf(xr[d], gw[d*CE + e], acc);
    g_logits[(size_t)tok*CE + e] = acc;
}

// ---------------- gating: softmax + top2 ----------------
__global__ void gate_kernel() {
    int t = blockIdx.x * 256 + threadIdx.x;
    if (t >= CBN) return;
    float lg[CE];
    float mx = -1e30f;
    #pragma unroll
    for (int e = 0; e < CE; e++) { lg[e] = g_logits[(size_t)t*CE + e]; mx = fmaxf(mx, lg[e]); }
    float sum = 0.f;
    #pragma unroll
    for (int e = 0; e < CE; e++) { lg[e] = __expf(lg[e] - mx); sum += lg[e]; }
    float inv = 1.f / sum;
    #pragma unroll
    for (int e = 0; e < CE; e++) { lg[e] *= inv; g_raw[(size_t)t*CE + e] = lg[e]; }
    int i1 = 0; float b1 = lg[0];
    #pragma unroll
    for (int e = 1; e < CE; e++) if (lg[e] > b1) { b1 = lg[e]; i1 = e; }
    int i2 = -1; float b2 = -1.f;
    #pragma unroll
    for (int e = 0; e < CE; e++) if (e != i1 && lg[e] > b2) { b2 = lg[e]; i2 = e; }
    float denom = b1 + b2 + 1e-9f;
    g_e1[t] = i1; g_e2[t] = i2;
    g_g1[t] = b1 / denom; g_g2[t] = b2 / denom;
}

// ---------------- route init ----------------
__global__ void routeinit_kernel() {
    int i = blockIdx.x * 256 + threadIdx.x;
    if (i < CEC) g_route[i] = -1;
}

// ---------------- capacity assignment (sequential per (b,e)) ----------------
__global__ void capacity_kernel() {
    int b = blockIdx.x;
    int e = threadIdx.x;
    if (e >= CE) return;
    int cnt = 0;
    for (int n = 0; n < CN; n++) {
        int t = b*CN + n;
        if (g_e1[t] == e) {
            int pos = cnt++;
            if (pos < CCAP) {
                g_s1[t] = pos;
                g_route[(e*CB + b)*CCAP + pos] = t;
            } else {
                g_s1[t] = -1;
                g_g1[t] = 0.f;
            }
        }
    }
    g_cnt1[b*CE + e] = cnt;
    int m1c = cnt < CCAP ? cnt : CCAP;
    int cnt2 = 0;
    for (int n = 0; n < CN; n++) {
        int t = b*CN + n;
        if (g_e2[t] == e) {
            int pos = cnt2++ + m1c;
            if (pos < CCAP) {
                g_s2[t] = pos;
                g_route[(e*CB + b)*CCAP + pos] = t;
            } else {
                g_s2[t] = -1;
                g_g2[t] = 0.f;
            }
        }
    }
}

// ---------------- gather tokens into expert slots (fp16 out) ----------------
__global__ void gather_h_kernel() {
    int row = blockIdx.x;
    int t = g_route[row];
    __half2* dst = (__half2*)(g_xinh + (size_t)row * CD);
    int i = threadIdx.x;  // 0..191
    if (t < 0) {
        __half2 z = __floats2half2_rn(0.f, 0.f);
        dst[2*i] = z; dst[2*i+1] = z;
    } else {
        float4 v = ((const float4*)(g_n2 + (size_t)t * CD))[i];
        dst[2*i]   = __floats2half2_rn(v.x, v.y);
        dst[2*i+1] = __floats2half2_rn(v.z, v.w);
    }
}

// ---------------- streaming fp32 -> fp16 convert (no transpose!) ----------------
template<bool SPLIT>
__global__ void convert_kernel(const float* __restrict__ in,
                               __half* __restrict__ hi,
                               __half* __restrict__ lo,
                               long n4, float scale) {
    long i = (long)blockIdx.x * blockDim.x + threadIdx.x;
    long stride = (long)gridDim.x * blockDim.x;
    for (; i < n4; i += stride) {
        float4 v = ((const float4*)in)[i];
        v.x *= scale; v.y *= scale; v.z *= scale; v.w *= scale;
        __half2 h0 = __floats2half2_rn(v.x, v.y);
        __half2 h1 = __floats2half2_rn(v.z, v.w);
        ((__half2*)hi)[2*i]   = h0;
        ((__half2*)hi)[2*i+1] = h1;
        if (SPLIT) {
            float2 f0 = __half22float2(h0), f1 = __half22float2(h1);
            ((__half2*)lo)[2*i]   = __floats2half2_rn(v.x - f0.x, v.y - f0.y);
            ((__half2*)lo)[2*i+1] = __floats2half2_rn(v.z - f1.x, v.w - f1.y);
        }
    }
}

// ---------------- weighted combine + residual 2 ----------------
__global__ void combine_kernel(float* __restrict__ out) {
    int t = blockIdx.x;
    int b = t / CN;
    const float4* hh = (const float4*)(g_h + (size_t)t * CD);
    float4 v = hh[threadIdx.x];
    int s1 = g_s1[t];
    if (s1 >= 0) {
        float gg = g_g1[t];
        const float4* x1 = (const float4*)(g_xo + ((size_t)(g_e1[t]*CB + b)*CCAP + s1) * CD);
        float4 a = x1[threadIdx.x];
        v.x = fmaf(gg, a.x, v.x); v.y = fmaf(gg, a.y, v.y);
        v.z = fmaf(gg, a.z, v.z); v.w = fmaf(gg, a.w, v.w);
    }
    int s2 = g_s2[t];
    if (s2 >= 0) {
        float gg = g_g2[t];
        const float4* x2 = (const float4*)(g_xo + ((size_t)(g_e2[t]*CB + b)*CCAP + s2) * CD);
        float4 a = x2[threadIdx.x];
        v.x = fmaf(gg, a.x, v.x); v.y = fmaf(gg, a.y, v.y);
        v.z = fmaf(gg, a.z, v.z); v.w = fmaf(gg, a.w, v.w);
    }
    ((float4*)out)[(size_t)t * (CD/4) + threadIdx.x] = v;
}

// ---------------- aux loss ----------------
__global__ void loss_kernel(float* __restrict__ out, int out_size) {
    int tid = threadIdx.x;
    int b = tid >> 4, e = tid & 15;
    float proxy = 0.f;
    for (int n = 0; n < CN; n++) proxy += g_raw[((size_t)(b*CN + n))*CE + e];
    proxy /= (float)CN;
    float dens = (float)g_cnt1[b*CE + e] / (float)CN;
    float v = proxy * dens;
    __shared__ float red[128];
    red[tid] = v;
    __syncthreads();
    for (int s = 64; s; s >>= 1) {
        if (tid < s) red[tid] += red[tid + s];
        __syncthreads();
    }
    if (tid == 0) {
        float loss = red[0] / (float)(CB*CE) * (float)(CE*CE) * 0.01f;
        const int base = CBN*CD;
        if (out_size > base) out[base] = loss;
        for (int i = base + 1; i < out_size; i++) out[i] = 0.f;
    }
}

// ---------------- launcher ----------------
extern "C" void kernel_launch(void* const* d_in, const int* in_sizes, int n_in,
                              void* d_out, int out_size) {
    const float* hid   = (const float*)d_in[0];
    const int*   mask  = (const int*)d_in[1];
    const float* ln0   = (const float*)d_in[2];
    const float* Wq    = (const float*)d_in[3];
    const float* Wk    = (const float*)d_in[4];
    const float* Wv    = (const float*)d_in[5];
    const float* Wo    = (const float*)d_in[6];
    const float* ln1   = (const float*)d_in[7];
    const float* gw    = (const float*)d_in[8];
    const float* ew1   = (const float*)d_in[9];
    const float* ew2   = (const float*)d_in[10];
    float* out = (float*)d_out;

    float *p_q, *p_k, *p_v, *p_h, *p_n2, *p_xo;
    __half *p_nh, *p_nl, *p_aoh, *p_aol;
    __half *p_wqh, *p_wql, *p_wkh, *p_wkl, *p_wvh, *p_wvl, *p_woh, *p_wol;
    __half *p_xinh, *p_midh, *p_w1h, *p_w2h;
    cudaGetSymbolAddress((void**)&p_q,    g_q);
    cudaGetSymbolAddress((void**)&p_k,    g_k);
    cudaGetSymbolAddress((void**)&p_v,    g_v);
    cudaGetSymbolAddress((void**)&p_h,    g_h);
    cudaGetSymbolAddress((void**)&p_n2,   g_n2);
    cudaGetSymbolAddress((void**)&p_xo,   g_xo);
    cudaGetSymbolAddress((void**)&p_nh,   g_nh);
    cudaGetSymbolAddress((void**)&p_nl,   g_nl);
    cudaGetSymbolAddress((void**)&p_aoh,  g_aoh);
    cudaGetSymbolAddress((void**)&p_aol,  g_aol);
    cudaGetSymbolAddress((void**)&p_wqh,  g_wqh);
    cudaGetSymbolAddress((void**)&p_wql,  g_wql);
    cudaGetSymbolAddress((void**)&p_wkh,  g_wkh);
    cudaGetSymbolAddress((void**)&p_wkl,  g_wkl);
    cudaGetSymbolAddress((void**)&p_wvh,  g_wvh);
    cudaGetSymbolAddress((void**)&p_wvl,  g_wvl);
    cudaGetSymbolAddress((void**)&p_woh,  g_woh);
    cudaGetSymbolAddress((void**)&p_wol,  g_wol);
    cudaGetSymbolAddress((void**)&p_xinh, g_xinh);
    cudaGetSymbolAddress((void**)&p_midh, g_midh);
    cudaGetSymbolAddress((void**)&p_w1h,  g_w1h);
    cudaGetSymbolAddress((void**)&p_w2h,  g_w2h);

    // ---- weight prep: pure streaming converts (layouts stay [K][N]) ----
    long nproj4 = (long)CD*CD/4;
    convert_kernel<true ><<<1024, 256>>>(Wq, p_wqh, p_wql, nproj4, WSCALE);
    convert_kernel<true ><<<1024, 256>>>(Wk, p_wkh, p_wkl, nproj4, WSCALE);
    convert_kernel<true ><<<1024, 256>>>(Wv, p_wvh, p_wvl, nproj4, WSCALE);
    convert_kernel<true ><<<1024, 256>>>(Wo, p_woh, p_wol, nproj4, WSCALE);
    long nff4 = (long)CE*CD*CDFF/4;
    convert_kernel<false><<<8192, 256>>>(ew1, p_w1h, nullptr, nff4, 1.0f);
    convert_kernel<false><<<8192, 256>>>(ew2, p_w2h, nullptr, nff4, 1.0f);

    // 1. RMSNorm 0 -> split fp16
    rmsnorm_kernel<1><<<CBN, 256>>>(hid, ln0, nullptr, p_nh, p_nl);

    // 2. Q/K/V projections: split-fp16 3-term tensor GEMM, fp32 out
    dim3 gproj(CD/128, CBN/128, 1);
    mma_gemm<3,false,false,false><<<gproj, 256>>>(p_nh, p_nl, p_wqh, p_wql, nullptr, p_q, CD, CD, WISCALE, 0, 0, 0);
    mma_gemm<3,false,false,false><<<gproj, 256>>>(p_nh, p_nl, p_wkh, p_wkl, nullptr, p_k, CD, CD, WISCALE, 0, 0, 0);
    mma_gemm<3,false,false,false><<<gproj, 256>>>(p_nh, p_nl, p_wvh, p_wvl, nullptr, p_v, CD, CD, WISCALE, 0, 0, 0);

    // 3. attention (fp32), writes split-fp16 ao
    attn_kernel<<<dim3(CN/128, CB*CH), 128>>>(mask);

    // 4. output projection + residual -> h (fp32)
    mma_gemm<3,false,true,false><<<gproj, 256>>>(p_aoh, p_aol, p_woh, p_wol, hid, p_h, CD, CD, WISCALE, 0, 0, 0);

    // 5. RMSNorm 1 -> fp32
    rmsnorm_kernel<0><<<CBN, 256>>>(p_h, ln1, p_n2, nullptr, nullptr);

    // 6. gating (fp32: routing bit-exact)
    logits_kernel<<<CBN/16, 256>>>(gw);
    gate_kernel<<<(CBN + 255)/256, 256>>>();
    routeinit_kernel<<<(CEC + 255)/256, 256>>>();
    capacity_kernel<<<CB, 32>>>();

    // 7. dispatch (fp16)
    gather_h_kernel<<<CEC, CD/4>>>();

    // 8. expert FFN (fp16 mma, fp32 accum; weights native [K][N])
    mma_gemm<1,true,false,true ><<<dim3(CDFF/128, CMZ/128, CE), 256>>>(
        p_xinh, nullptr, p_w1h, nullptr, nullptr, p_midh, CDFF, CD, 1.0f,
        (long)CMZ*CD, (long)CD*CDFF, (long)CMZ*CDFF);
    mma_gemm<1,false,false,false><<<dim3(CD/128, CMZ/128, CE), 256>>>(
        p_midh, nullptr, p_w2h, nullptr, nullptr, p_xo, CD, CDFF, 1.0f,
        (long)CMZ*CDFF, (long)CDFF*CD, (long)CMZ*CD);

    // 9. combine + residual 2
    combine_kernel<<<CBN, CD/4>>>(out);

    // 10. aux loss
    loss_kernel<<<1, 128>>>(out, out_size);
}

// round 11
// speedup vs baseline: 3.8793x; 1.4579x over previous
#include <cuda_runtime.h>
#include <cuda_fp16.h>
#include <cstdint>

// ---------------- problem constants ----------------
#define CB   8
#define CN   1024
#define CD   768
#define CH   12
#define CDKV 64
#define CDFF 3072
#define CE   16
#define CCAP 128
#define CBN  (CB*CN)          // 8192 tokens
#define CEC  (CE*CB*CCAP)     // 16384 expert slots
#define CMZ  (CB*CCAP)        // 1024 rows per expert
#define WSCALE 32.0f
#define WISCALE (1.0f/32.0f)

// ---------------- device scratch ----------------
static __device__ float g_h      [CBN*CD];
static __device__ float g_n2     [CBN*CD];
static __device__ float g_logits [CBN*CE];
static __device__ float g_raw    [CBN*CE];
static __device__ int   g_e1[CBN], g_e2[CBN], g_s1[CBN], g_s2[CBN];
static __device__ float g_g1[CBN], g_g2[CBN];
static __device__ int   g_cnt1[CB*CE];
static __device__ int   g_route[CEC];
static __device__ float g_xo [CEC*CD];
// split-fp16 activations
static __device__ __half g_nh [CBN*CD], g_nl [CBN*CD];     // normed hi/lo
static __device__ __half g_qh [CBN*CD], g_ql [CBN*CD];     // q hi/lo
static __device__ __half g_kh [CBN*CD], g_kl [CBN*CD];     // k hi/lo
static __device__ __half g_vh [CBN*CD], g_vl [CBN*CD];     // v hi/lo
static __device__ __half g_aoh[CBN*CD], g_aol[CBN*CD];     // attn out hi/lo
// fp16 projection weights, native [K][N] layout, scaled by WSCALE, split hi/lo
static __device__ __half g_wqh[CD*CD], g_wql[CD*CD];
static __device__ __half g_wkh[CD*CD], g_wkl[CD*CD];
static __device__ __half g_wvh[CD*CD], g_wvl[CD*CD];
static __device__ __half g_woh[CD*CD], g_wol[CD*CD];
// fp16 MoE path (weights native [K][N])
static __device__ __half g_xinh[CEC*CD];
static __device__ __half g_midh[CEC*CDFF];
static __device__ __half g_w1h [CE*CD*CDFF];   // [e][D][DFF]
static __device__ __half g_w2h [CE*CDFF*CD];   // [e][DFF][D]

// ================= portable PTX helpers =================
__device__ __forceinline__ uint32_t smem_u32(const void* p) {
    uint32_t a;
    asm("{ .reg .u64 t; cvta.to.shared.u64 t, %1; cvt.u32.u64 %0, t; }" : "=r"(a) : "l"(p));
    return a;
}
#define CP16(dst, src) \
    asm volatile("cp.async.cg.shared.global [%0], [%1], 16;" :: "r"(dst), "l"(src) : "memory")
#define CPCOMMIT() asm volatile("cp.async.commit_group;" ::: "memory")
#define CPWAIT0()  asm volatile("cp.async.wait_group 0;" ::: "memory")
#define LDSM4(r0, r1, r2, r3, addr) \
    asm volatile("ldmatrix.sync.aligned.m8n8.x4.shared.b16 {%0,%1,%2,%3}, [%4];" \
        : "=r"(r0), "=r"(r1), "=r"(r2), "=r"(r3) : "r"(addr))
#define LDSM4T(r0, r1, r2, r3, addr) \
    asm volatile("ldmatrix.sync.aligned.m8n8.x4.trans.shared.b16 {%0,%1,%2,%3}, [%4];" \
        : "=r"(r0), "=r"(r1), "=r"(r2), "=r"(r3) : "r"(addr))
#define MMAH(c, a, b0v, b1v) \
    asm volatile("mma.sync.aligned.m16n8k16.row.col.f32.f16.f16.f32 " \
        "{%0,%1,%2,%3}, {%4,%5,%6,%7}, {%8,%9}, {%0,%1,%2,%3};" \
        : "+f"((c)[0]), "+f"((c)[1]), "+f"((c)[2]), "+f"((c)[3]) \
        : "r"((a)[0]), "r"((a)[1]), "r"((a)[2]), "r"((a)[3]), "r"(b0v), "r"(b1v))

// FMA-pipe exp (no MUFU): magic-number round + degree-6 2^f Taylor + exponent add.
// rel err ~1.2e-7 on x<=0; clamp at -80 keeps the bit-trick in normal range.
__device__ __forceinline__ float fast_exp(float x) {
    x = fmaxf(x, -80.f);
    float t  = x * 1.44269504f;
    float tt = t + 12582912.f;               // round-to-nearest int in mantissa
    int   ei = __float_as_int(tt) - 0x4B400000;
    float n  = tt - 12582912.f;
    float f  = t - n;                        // [-0.5, 0.5]
    float u  = f * 0.69314718f;
    float p  = 1.f + u*(1.f + u*(0.5f + u*(0.16666667f + u*(0.041666668f +
               u*(0.0083333338f + u*0.0013888889f)))));
    return __int_as_float(__float_as_int(p) + (ei << 23));
}

// ---------------- RMSNorm (T5, eps=1e-6); OUTMODE 0=fp32, 1=split fp16 ----------------
template<int OUTMODE>
__global__ void rmsnorm_kernel(const float* __restrict__ x,
                               const float* __restrict__ w,
                               float* __restrict__ y,
                               __half* __restrict__ yh,
                               __half* __restrict__ yl) {
    int row = blockIdx.x;
    const float* xr = x + (size_t)row * CD;
    float s = 0.f;
    for (int i = threadIdx.x; i < CD; i += 256) { float v = xr[i]; s = fmaf(v, v, s); }
    for (int o = 16; o; o >>= 1) s += __shfl_xor_sync(0xffffffffu, s, o);
    __shared__ float red[8];
    __shared__ float invs;
    if ((threadIdx.x & 31) == 0) red[threadIdx.x >> 5] = s;
    __syncthreads();
    if (threadIdx.x == 0) {
        float tot = 0.f;
        #pragma unroll
        for (int i = 0; i < 8; i++) tot += red[i];
        invs = rsqrtf(tot / CD + 1e-6f);
    }
    __syncthreads();
    float inv = invs;
    for (int i = threadIdx.x; i < CD; i += 256) {
        float v = xr[i] * inv * w[i];
        if (OUTMODE == 0) {
            y[(size_t)row*CD + i] = v;
        } else {
            __half hv = __float2half_rn(v);
            yh[(size_t)row*CD + i] = hv;
            yl[(size_t)row*CD + i] = __float2half_rn(v - __half2float(hv));
        }
    }
}

// ---------------- unified fp16 tensor-core GEMM ----------------
// C[M,Nn](+z) = scale * (A[M,K] @ B[K,Nn]) (+Rz) (+relu), fp32 accum.
// OUTM: 0=fp32, 1=fp16, 2=split fp16 (hi->Cout, lo->Cout2).
template<int TERMS, bool RELU, bool RESID, int OUTM>
__global__ __launch_bounds__(256) void mma_gemm(
    const __half* __restrict__ Ahi, const __half* __restrict__ Alo,
    const __half* __restrict__ Bhi, const __half* __restrict__ Blo,
    const float* __restrict__ Rz, void* __restrict__ Cout, void* __restrict__ Cout2,
    int Nn, int K, float scale, long zA, long zB, long zC)
{
    constexpr int BK    = (TERMS == 3) ? 16 : 32;
    constexpr int NA    = (TERMS == 3) ? 2 : 1;
    constexpr int LDSA  = BK + 8;
    constexpr int LDSB  = 136;
    constexpr uint32_t ATILEB = 128u * LDSA * 2;
    constexpr uint32_t BTILEB = (uint32_t)BK * LDSB * 2;
    constexpr uint32_t STAGEB = NA * (ATILEB + BTILEB);
    constexpr int ACH = 128 * (BK / 8);
    constexpr int BCH = BK * 16;
    constexpr int CPT = NA * (ACH + BCH) / 256;
    __shared__ __align__(16) unsigned char sm[2 * STAGEB];

    long e = blockIdx.z;
    int m0 = blockIdx.y * 128, n0 = blockIdx.x * 128;

    int tid = threadIdx.x, lane = tid & 31, wid = tid >> 5;
    int warp_row = (wid & 3) * 32, warp_col = (wid >> 2) * 64;
    uint32_t sb = smem_u32(sm);

    const __half* cur[CPT];
    long gstep[CPT];
    uint32_t sd[CPT];
    #pragma unroll
    for (int j = 0; j < CPT; j++) {
        int c = tid + j * 256;
        if (c < NA * ACH) {
            int tile = c / ACH;
            int rr = (c % ACH) / (BK / 8);
            int c8 = c % (BK / 8);
            sd[j] = tile * (ATILEB + BTILEB) + (uint32_t)(rr * LDSA + c8 * 8) * 2;
            const __half* src = (tile == 0 ? Ahi : Alo);
            cur[j] = src + e * zA + (long)(m0 + rr) * K + c8 * 8;
            gstep[j] = BK;
        } else {
            int c2 = c - NA * ACH;
            int tile = c2 / BCH;
            int rr = (c2 % BCH) / 16;
            int c8 = c2 % 16;
            sd[j] = tile * (ATILEB + BTILEB) + ATILEB + (uint32_t)(rr * LDSB + c8 * 8) * 2;
            const __half* src = (tile == 0 ? Bhi : Blo);
            cur[j] = src + e * zB + (long)rr * Nn + n0 + c8 * 8;
            gstep[j] = (long)BK * Nn;
        }
    }

    int nk = K / BK;
    #pragma unroll
    for (int j = 0; j < CPT; j++) { CP16(sb + sd[j], cur[j]); cur[j] += gstep[j]; }
    CPCOMMIT();

    float acc[2][8][4];
    #pragma unroll
    for (int mi = 0; mi < 2; mi++)
        #pragma unroll
        for (int ni = 0; ni < 8; ni++)
            #pragma unroll
            for (int j = 0; j < 4; j++) acc[mi][ni][j] = 0.f;

    int lm_r = lane & 15, lm_k = (lane >> 4) << 3;

    for (int kc = 0; kc < nk; kc++) {
        CPWAIT0();
        __syncthreads();
        if (kc + 1 < nk) {
            uint32_t s2 = (uint32_t)((kc + 1) & 1) * STAGEB;
            #pragma unroll
            for (int j = 0; j < CPT; j++) { CP16(sb + s2 + sd[j], cur[j]); cur[j] += gstep[j]; }
            CPCOMMIT();
        }
        uint32_t st = sb + (uint32_t)(kc & 1) * STAGEB;
        #pragma unroll
        for (int k16 = 0; k16 < BK; k16 += 16) {
            uint32_t afh[2][4], afl[2][4];
            #pragma unroll
            for (int mi = 0; mi < 2; mi++) {
                int row = warp_row + mi*16 + lm_r;
                LDSM4(afh[mi][0], afh[mi][1], afh[mi][2], afh[mi][3],
                      st + (uint32_t)(row*LDSA + k16 + lm_k) * 2);
                if (TERMS == 3)
                    LDSM4(afl[mi][0], afl[mi][1], afl[mi][2], afl[mi][3],
                          st + (ATILEB + BTILEB) + (uint32_t)(row*LDSA + k16 + lm_k) * 2);
            }
            #pragma unroll
            for (int nt = 0; nt < 4; nt++) {
                uint32_t boff = (uint32_t)((k16 + lm_r) * LDSB + warp_col + nt*16 + lm_k) * 2;
                uint32_t bh[4], bl[4];
                LDSM4T(bh[0], bh[1], bh[2], bh[3], st + ATILEB + boff);
                if (TERMS == 3)
                    LDSM4T(bl[0], bl[1], bl[2], bl[3],
                           st + (ATILEB + BTILEB) + ATILEB + boff);
                #pragma unroll
                for (int mi = 0; mi < 2; mi++)
                    #pragma unroll
                    for (int hh = 0; hh < 2; hh++) {
                        float* cc = acc[mi][nt*2 + hh];
                        MMAH(cc, afh[mi], bh[2*hh], bh[2*hh + 1]);
                        if (TERMS == 3) {
                            MMAH(cc, afh[mi], bl[2*hh], bl[2*hh + 1]);
                            MMAH(cc, afl[mi], bh[2*hh], bh[2*hh + 1]);
                        }
                    }
            }
        }
    }

    int eg = lane >> 2, et = lane & 3;
    #pragma unroll
    for (int mi = 0; mi < 2; mi++) {
        #pragma unroll
        for (int ni = 0; ni < 8; ni++) {
            long r  = m0 + warp_row + mi*16 + eg;
            long cc = n0 + warp_col + ni*8 + et*2;
            float v0 = acc[mi][ni][0]*scale, v1 = acc[mi][ni][1]*scale;
            float v2 = acc[mi][ni][2]*scale, v3 = acc[mi][ni][3]*scale;
            if (RESID) {
                float2 r0 = *(const float2*)(Rz + r*Nn + cc);
                float2 r1 = *(const float2*)(Rz + (r+8)*Nn + cc);
                v0 += r0.x; v1 += r0.y; v2 += r1.x; v3 += r1.y;
            }
            if (RELU) {
                v0 = fmaxf(v0, 0.f); v1 = fmaxf(v1, 0.f);
                v2 = fmaxf(v2, 0.f); v3 = fmaxf(v3, 0.f);
            }
            if (OUTM == 0) {
                float* C = (float*)Cout + e*zC;
                *(float2*)(C + r*Nn + cc)     = make_float2(v0, v1);
                *(float2*)(C + (r+8)*Nn + cc) = make_float2(v2, v3);
            } else if (OUTM == 1) {
                __half* C = (__half*)Cout + e*zC;
                *(__half2*)(C + r*Nn + cc)     = __floats2half2_rn(v0, v1);
                *(__half2*)(C + (r+8)*Nn + cc) = __floats2half2_rn(v2, v3);
            } else {
                __half* C  = (__half*)Cout  + e*zC;
                __half* C2 = (__half*)Cout2 + e*zC;
                __half2 h0 = __floats2half2_rn(v0, v1);
                float2 f0 = __half22float2(h0);
                *(__half2*)(C  + r*Nn + cc) = h0;
                *(__half2*)(C2 + r*Nn + cc) = __floats2half2_rn(v0 - f0.x, v1 - f0.y);
                __half2 h1 = __floats2half2_rn(v2, v3);
                float2 f1 = __half22float2(h1);
                *(__half2*)(C  + (r+8)*Nn + cc) = h1;
                *(__half2*)(C2 + (r+8)*Nn + cc) = __floats2half2_rn(v2 - f1.x, v3 - f1.y);
            }
        }
    }
}

// ---------------- tensor-core flash attention (split-fp16 3-term, FMA-pipe exp) ----------------
// CTA: 128 q rows, 8 warps x 16 rows. KV in 64-key tiles, 2-stage cp.async.
__global__ __launch_bounds__(256) void tc_attn(const int* __restrict__ mask) {
    extern __shared__ __align__(16) unsigned char sm[];
    constexpr uint32_t LDQ = 72;              // halves: 144B rows, ldsm conflict-free
    constexpr uint32_t QT  = 128*LDQ*2;       // 18432B per Q tile
    constexpr uint32_t KVT = 64*LDQ*2;        // 9216B per KV array
    constexpr uint32_t KVS = 4*KVT;           // Kh,Kl,Vh,Vl per stage
    constexpr uint32_t KVB = 2*QT;
    constexpr uint32_t MBB = KVB + 2*KVS;     // mask bias area (1024 floats)

    int tid = threadIdx.x, lane = tid & 31, w = tid >> 5;
    int g = lane >> 2, t4 = lane & 3;
    int lm_r = lane & 15, lm_k = (lane >> 4) << 3;
    int bh = blockIdx.y, b = bh / CH, hh = bh % CH;
    int q0 = blockIdx.x * 128;
    uint32_t sb = smem_u32(sm);
    float* MBf = (float*)(sm + MBB);

    // mask bias for all 1024 keys (plain stores; covered by prologue sync)
    for (int i = tid; i < CN; i += 256)
        MBf[i] = (mask[b*CN + i] != 0) ? 0.f : -1e9f;

    // prologue: Q(hi+lo) + KV stage 0
    #pragma unroll
    for (int j = 0; j < 8; j++) {
        int c = tid + j*256;
        int arr = c >> 10, idx = c & 1023;
        int row = idx >> 3, ch = idx & 7;
        const __half* src = (arr ? g_ql : g_qh) + ((size_t)(b*CN + q0 + row)*CH + hh)*CDKV + ch*8;
        CP16(sb + (uint32_t)arr*QT + (uint32_t)(row*LDQ + ch*8)*2, src);
    }
    #pragma unroll
    for (int j = 0; j < 8; j++) {
        int c = tid + j*256;
        int arr = c >> 9, idx = c & 511;
        int row = idx >> 3, ch = idx & 7;
        const __half* src = (arr==0 ? g_kh : arr==1 ? g_kl : arr==2 ? g_vh : g_vl)
                          + ((size_t)(b*CN + row)*CH + hh)*CDKV + ch*8;
        CP16(sb + KVB + (uint32_t)arr*KVT + (uint32_t)(row*LDQ + ch*8)*2, src);
    }
    CPCOMMIT();
    CPWAIT0();
    __syncthreads();

    // Q fragments (resident in registers)
    uint32_t qfh[4][4], qfl[4][4];
    #pragma unroll
    for (int kc = 0; kc < 4; kc++) {
        uint32_t a = sb + (uint32_t)((w*16 + lm_r)*LDQ + kc*16 + lm_k)*2;
        LDSM4(qfh[kc][0], qfh[kc][1], qfh[kc][2], qfh[kc][3], a);
        LDSM4(qfl[kc][0], qfl[kc][1], qfl[kc][2], qfl[kc][3], a + QT);
    }

    float m_lo = -1e30f, m_hi = -1e30f, l_lo = 0.f, l_hi = 0.f;
    float o[8][4];
    #pragma unroll
    for (int nd = 0; nd < 8; nd++)
        #pragma unroll
        for (int j = 0; j < 4; j++) o[nd][j] = 0.f;

    for (int kt = 0; kt < 16; kt++) {
        if (kt > 0) { CPWAIT0(); __syncthreads(); }
        if (kt + 1 < 16) {
            uint32_t s2 = (uint32_t)((kt+1) & 1) * KVS;
            #pragma unroll
            for (int j = 0; j < 8; j++) {
                int c = tid + j*256;
                int arr = c >> 9, idx = c & 511;
                int row = idx >> 3, ch = idx & 7;
                const __half* src = (arr==0 ? g_kh : arr==1 ? g_kl : arr==2 ? g_vh : g_vl)
                                  + ((size_t)(b*CN + (kt+1)*64 + row)*CH + hh)*CDKV + ch*8;
                CP16(sb + KVB + s2 + (uint32_t)arr*KVT + (uint32_t)(row*LDQ + ch*8)*2, src);
            }
            CPCOMMIT();
        }
        uint32_t kb = sb + KVB + (uint32_t)(kt & 1) * KVS;

        // S = Q K^T, 3-term (hh + hl + lh)
        float cs[8][4];
        #pragma unroll
        for (int ni = 0; ni < 8; ni++)
            #pragma unroll
            for (int j = 0; j < 4; j++) cs[ni][j] = 0.f;
        #pragma unroll
        for (int kc = 0; kc < 4; kc++) {
            #pragma unroll
            for (int nt = 0; nt < 4; nt++) {
                uint32_t ka = kb + (uint32_t)((nt*16 + lm_r)*LDQ + kc*16 + lm_k)*2;
                uint32_t kfh[4], kfl[4];
                LDSM4(kfh[0], kfh[1], kfh[2], kfh[3], ka);
                LDSM4(kfl[0], kfl[1], kfl[2], kfl[3], ka + KVT);
                #pragma unroll
                for (int hx = 0; hx < 2; hx++) {
                    float* cc = cs[nt*2 + hx];
                    MMAH(cc, qfh[kc], kfh[hx], kfh[2+hx]);
                    MMAH(cc, qfh[kc], kfl[hx], kfl[2+hx]);
                    MMAH(cc, qfl[kc], kfh[hx], kfh[2+hx]);
                }
            }
        }
        // bias + row max (quad reduce over t4)
        float tl = -1e30f, th = -1e30f;
        #pragma unroll
        for (int ni = 0; ni < 8; ni++) {
            float b0 = MBf[kt*64 + ni*8 + 2*t4];
            float b1 = MBf[kt*64 + ni*8 + 2*t4 + 1];
            cs[ni][0] += b0; cs[ni][1] += b1; cs[ni][2] += b0; cs[ni][3] += b1;
            tl = fmaxf(tl, fmaxf(cs[ni][0], cs[ni][1]));
            th = fmaxf(th, fmaxf(cs[ni][2], cs[ni][3]));
        }
        tl = fmaxf(tl, __shfl_xor_sync(0xffffffffu, tl, 1));
        tl = fmaxf(tl, __shfl_xor_sync(0xffffffffu, tl, 2));
        th = fmaxf(th, __shfl_xor_sync(0xffffffffu, th, 1));
        th = fmaxf(th, __shfl_xor_sync(0xffffffffu, th, 2));
        float mn_lo = fmaxf(m_lo, tl), mn_hi = fmaxf(m_hi, th);
        float sc_lo = fast_exp(m_lo - mn_lo), sc_hi = fast_exp(m_hi - mn_hi);
        m_lo = mn_lo; m_hi = mn_hi;
        l_lo *= sc_lo; l_hi *= sc_hi;
        #pragma unroll
        for (int nd = 0; nd < 8; nd++) {
            o[nd][0] *= sc_lo; o[nd][1] *= sc_lo;
            o[nd][2] *= sc_hi; o[nd][3] *= sc_hi;
        }
        // p = exp(s - m), packed as split-fp16 A-fragments (C-layout == A-layout identity)
        uint32_t pfh[4][4], pfl[4][4];
        #pragma unroll
        for (int j = 0; j < 4; j++) {
            float a0 = fast_exp(cs[2*j][0] - mn_lo),   a1 = fast_exp(cs[2*j][1] - mn_lo);
            float a2 = fast_exp(cs[2*j][2] - mn_hi),   a3 = fast_exp(cs[2*j][3] - mn_hi);
            float b0 = fast_exp(cs[2*j+1][0] - mn_lo), b1 = fast_exp(cs[2*j+1][1] - mn_lo);
            float b2 = fast_exp(cs[2*j+1][2] - mn_hi), b3 = fast_exp(cs[2*j+1][3] - mn_hi);
            l_lo += (a0 + a1) + (b0 + b1);
            l_hi += (a2 + a3) + (b2 + b3);
            __half2 h; float2 f;
            h = __floats2half2_rn(a0, a1); f = __half22float2(h);
            pfh[j][0] = *(uint32_t*)&h;
            { __half2 lo2 = __floats2half2_rn(a0 - f.x, a1 - f.y); pfl[j][0] = *(uint32_t*)&lo2; }
            h = __floats2half2_rn(a2, a3); f = __half22float2(h);
            pfh[j][1] = *(uint32_t*)&h;
            { __half2 lo2 = __floats2half2_rn(a2 - f.x, a3 - f.y); pfl[j][1] = *(uint32_t*)&lo2; }
            h = __floats2half2_rn(b0, b1); f = __half22float2(h);
            pfh[j][2] = *(uint32_t*)&h;
            { __half2 lo2 = __floats2half2_rn(b0 - f.x, b1 - f.y); pfl[j][2] = *(uint32_t*)&lo2; }
            h = __floats2half2_rn(b2, b3); f = __half22float2(h);
            pfh[j][3] = *(uint32_t*)&h;
            { __half2 lo2 = __floats2half2_rn(b2 - f.x, b3 - f.y); pfl[j][3] = *(uint32_t*)&lo2; }
        }
        // out += P V, 3-term; V tile is [64 k][64 d] -> trans ldsm
        #pragma unroll
        for (int j = 0; j < 4; j++) {
            #pragma unroll
            for (int nt = 0; nt < 4; nt++) {
                uint32_t va = kb + 2*KVT + (uint32_t)((j*16 + lm_r)*LDQ + nt*16 + lm_k)*2;
                uint32_t vfh[4], vfl[4];
                LDSM4T(vfh[0], vfh[1], vfh[2], vfh[3], va);
                LDSM4T(vfl[0], vfl[1], vfl[2], vfl[3], va + KVT);
                #pragma unroll
                for (int hx = 0; hx < 2; hx++) {
                    float* cc = o[nt*2 + hx];
                    MMAH(cc, pfh[j], vfh[2*hx], vfh[2*hx+1]);
                    MMAH(cc, pfh[j], vfl[2*hx], vfl[2*hx+1]);
                    MMAH(cc, pfl[j], vfh[2*hx], vfh[2*hx+1]);
                }
            }
        }
    }

    // finalize
    l_lo += __shfl_xor_sync(0xffffffffu, l_lo, 1);
    l_lo += __shfl_xor_sync(0xffffffffu, l_lo, 2);
    l_hi += __shfl_xor_sync(0xffffffffu, l_hi, 1);
    l_hi += __shfl_xor_sync(0xffffffffu, l_hi, 2);
    float il = 1.f / l_lo, ih = 1.f / l_hi;
    int r_lo = q0 + w*16 + g, r_hi = r_lo + 8;
    #pragma unroll
    for (int nd = 0; nd < 8; nd++) {
        int col = nd*8 + 2*t4;
        size_t o_lo = ((size_t)(b*CN + r_lo)*CH + hh)*CDKV + col;
        size_t o_hi = ((size_t)(b*CN + r_hi)*CH + hh)*CDKV + col;
        float v0 = o[nd][0]*il, v1 = o[nd][1]*il;
        float v2 = o[nd][2]*ih, v3 = o[nd][3]*ih;
        __half2 h0 = __floats2half2_rn(v0, v1);
        float2 f0 = __half22float2(h0);
        *(__half2*)(g_aoh + o_lo) = h0;
        *(__half2*)(g_aol + o_lo) = __floats2half2_rn(v0 - f0.x, v1 - f0.y);
        __half2 h1 = __floats2half2_rn(v2, v3);
        float2 f1 = __half22float2(h1);
        *(__half2*)(g_aoh + o_hi) = h1;
        *(__half2*)(g_aol + o_hi) = __floats2half2_rn(v2 - f1.x, v3 - f1.y);
    }
}
#define TCATTN_SMEM (2*(128*72*2) + 2*4*(64*72*2) + 1024*4)

// ---------------- gate logits (fp32: routing exactness) ----------------
__global__ void logits_kernel(const float* __restrict__ gw) {
    int tid = threadIdx.x;
    int tok = blockIdx.x * 16 + (tid >> 4);
    int e = tid & 15;
    const float* xr = g_n2 + (size_t)tok * CD;
    float acc = 0.f;
    #pragma unroll 8
    for (int d = 0; d < CD; d++) acc = fmaf(xr[d], gw[d*CE + e], acc);
    g_logits[(size_t)tok*CE + e] = acc;
}

// ---------------- gating: softmax + top2 ----------------
__global__ void gate_kernel() {
    int t = blockIdx.x * 256 + threadIdx.x;
    if (t >= CBN) return;
    float lg[CE];
    float mx = -1e30f;
    #pragma unroll
    for (int e = 0; e < CE; e++) { lg[e] = g_logits[(size_t)t*CE + e]; mx = fmaxf(mx, lg[e]); }
    float sum = 0.f;
    #pragma unroll
    for (int e = 0; e < CE; e++) { lg[e] = __expf(lg[e] - mx); sum += lg[e]; }
    float inv = 1.f / sum;
    #pragma unroll
    for (int e = 0; e < CE; e++) { lg[e] *= inv; g_raw[(size_t)t*CE + e] = lg[e]; }
    int i1 = 0; float b1 = lg[0];
    #pragma unroll
    for (int e = 1; e < CE; e++) if (lg[e] > b1) { b1 = lg[e]; i1 = e; }
    int i2 = -1; float b2 = -1.f;
    #pragma unroll
    for (int e = 0; e < CE; e++) if (e != i1 && lg[e] > b2) { b2 = lg[e]; i2 = e; }
    float denom = b1 + b2 + 1e-9f;
    g_e1[t] = i1; g_e2[t] = i2;
    g_g1[t] = b1 / denom; g_g2[t] = b2 / denom;
}

// ---------------- route init ----------------
__global__ void routeinit_kernel() {
    int i = blockIdx.x * 256 + threadIdx.x;
    if (i < CEC) g_route[i] = -1;
}

// ---------------- capacity assignment (sequential per (b,e)) ----------------
__global__ void capacity_kernel() {
    int b = blockIdx.x;
    int e = threadIdx.x;
    if (e >= CE) return;
    int cnt = 0;
    for (int n = 0; n < CN; n++) {
        int t = b*CN + n;
        if (g_e1[t] == e) {
            int pos = cnt++;
            if (pos < CCAP) {
                g_s1[t] = pos;
                g_route[(e*CB + b)*CCAP + pos] = t;
            } else {
                g_s1[t] = -1;
                g_g1[t] = 0.f;
            }
        }
    }
    g_cnt1[b*CE + e] = cnt;
    int m1c = cnt < CCAP ? cnt : CCAP;
    int cnt2 = 0;
    for (int n = 0; n < CN; n++) {
        int t = b*CN + n;
        if (g_e2[t] == e) {
            int pos = cnt2++ + m1c;
            if (pos < CCAP) {
                g_s2[t] = pos;
                g_route[(e*CB + b)*CCAP + pos] = t;
            } else {
                g_s2[t] = -1;
                g_g2[t] = 0.f;
            }
        }
    }
}

// ---------------- gather tokens into expert slots (fp16 out) ----------------
__global__ void gather_h_kernel() {
    int row = blockIdx.x;
    int t = g_route[row];
    __half2* dst = (__half2*)(g_xinh + (size_t)row * CD);
    int i = threadIdx.x;
    if (t < 0) {
        __half2 z = __floats2half2_rn(0.f, 0.f);
        dst[2*i] = z; dst[2*i+1] = z;
    } else {
        float4 v = ((const float4*)(g_n2 + (size_t)t * CD))[i];
        dst[2*i]   = __floats2half2_rn(v.x, v.y);
        dst[2*i+1] = __floats2half2_rn(v.z, v.w);
    }
}

// ---------------- streaming fp32 -> fp16 convert ----------------
template<bool SPLIT>
__global__ void convert_kernel(const float* __restrict__ in,
                               __half* __restrict__ hi,
                               __half* __restrict__ lo,
                               long n4, float scale) {
    long i = (long)blockIdx.x * blockDim.x + threadIdx.x;
    long stride = (long)gridDim.x * blockDim.x;
    for (; i < n4; i += stride) {
        float4 v = ((const float4*)in)[i];
        v.x *= scale; v.y *= scale; v.z *= scale; v.w *= scale;
        __half2 h0 = __floats2half2_rn(v.x, v.y);
        __half2 h1 = __floats2half2_rn(v.z, v.w);
        ((__half2*)hi)[2*i]   = h0;
        ((__half2*)hi)[2*i+1] = h1;
        if (SPLIT) {
            float2 f0 = __half22float2(h0), f1 = __half22float2(h1);
            ((__half2*)lo)[2*i]   = __floats2half2_rn(v.x - f0.x, v.y - f0.y);
            ((__half2*)lo)[2*i+1] = __floats2half2_rn(v.z - f1.x, v.w - f1.y);
        }
    }
}

// ---------------- weighted combine + residual 2 ----------------
__global__ void combine_kernel(float* __restrict__ out) {
    int t = blockIdx.x;
    int b = t / CN;
    const float4* hh = (const float4*)(g_h + (size_t)t * CD);
    float4 v = hh[threadIdx.x];
    int s1 = g_s1[t];
    if (s1 >= 0) {
        float gg = g_g1[t];
        const float4* x1 = (const float4*)(g_xo + ((size_t)(g_e1[t]*CB + b)*CCAP + s1) * CD);
        float4 a = x1[threadIdx.x];
        v.x = fmaf(gg, a.x, v.x); v.y = fmaf(gg, a.y, v.y);
        v.z = fmaf(gg, a.z, v.z); v.w = fmaf(gg, a.w, v.w);
    }
    int s2 = g_s2[t];
    if (s2 >= 0) {
        float gg = g_g2[t];
        const float4* x2 = (const float4*)(g_xo + ((size_t)(g_e2[t]*CB + b)*CCAP + s2) * CD);
        float4 a = x2[threadIdx.x];
        v.x = fmaf(gg, a.x, v.x); v.y = fmaf(gg, a.y, v.y);
        v.z = fmaf(gg, a.z, v.z); v.w = fmaf(gg, a.w, v.w);
    }
    ((float4*)out)[(size_t)t * (CD/4) + threadIdx.x] = v;
}

// ---------------- aux loss ----------------
__global__ void loss_kernel(float* __restrict__ out, int out_size) {
    int tid = threadIdx.x;
    int b = tid >> 4, e = tid & 15;
    float proxy = 0.f;
    for (int n = 0; n < CN; n++) proxy += g_raw[((size_t)(b*CN + n))*CE + e];
    proxy /= (float)CN;
    float dens = (float)g_cnt1[b*CE + e] / (float)CN;
    float v = proxy * dens;
    __shared__ float red[128];
    red[tid] = v;
    __syncthreads();
    for (int s = 64; s; s >>= 1) {
        if (tid < s) red[tid] += red[tid + s];
        __syncthreads();
    }
    if (tid == 0) {
        float loss = red[0] / (float)(CB*CE) * (float)(CE*CE) * 0.01f;
        const int base = CBN*CD;
        if (out_size > base) out[base] = loss;
        for (int i = base + 1; i < out_size; i++) out[i] = 0.f;
    }
}

// ---------------- launcher ----------------
extern "C" void kernel_launch(void* const* d_in, const int* in_sizes, int n_in,
                              void* d_out, int out_size) {
    const float* hid   = (const float*)d_in[0];
    const int*   mask  = (const int*)d_in[1];
    const float* ln0   = (const float*)d_in[2];
    const float* Wq    = (const float*)d_in[3];
    const float* Wk    = (const float*)d_in[4];
    const float* Wv    = (const float*)d_in[5];
    const float* Wo    = (const float*)d_in[6];
    const float* ln1   = (const float*)d_in[7];
    const float* gw    = (const float*)d_in[8];
    const float* ew1   = (const float*)d_in[9];
    const float* ew2   = (const float*)d_in[10];
    float* out = (float*)d_out;

    float *p_h, *p_n2, *p_xo;
    __half *p_nh, *p_nl, *p_qh, *p_ql, *p_kh, *p_kl, *p_vh, *p_vl, *p_aoh, *p_aol;
    __half *p_wqh, *p_wql, *p_wkh, *p_wkl, *p_wvh, *p_wvl, *p_woh, *p_wol;
    __half *p_xinh, *p_midh, *p_w1h, *p_w2h;
    cudaGetSymbolAddress((void**)&p_h,    g_h);
    cudaGetSymbolAddress((void**)&p_n2,   g_n2);
    cudaGetSymbolAddress((void**)&p_xo,   g_xo);
    cudaGetSymbolAddress((void**)&p_nh,   g_nh);
    cudaGetSymbolAddress((void**)&p_nl,   g_nl);
    cudaGetSymbolAddress((void**)&p_qh,   g_qh);
    cudaGetSymbolAddress((void**)&p_ql,   g_ql);
    cudaGetSymbolAddress((void**)&p_kh,   g_kh);
    cudaGetSymbolAddress((void**)&p_kl,   g_kl);
    cudaGetSymbolAddress((void**)&p_vh,   g_vh);
    cudaGetSymbolAddress((void**)&p_vl,   g_vl);
    cudaGetSymbolAddress((void**)&p_aoh,  g_aoh);
    cudaGetSymbolAddress((void**)&p_aol,  g_aol);
    cudaGetSymbolAddress((void**)&p_wqh,  g_wqh);
    cudaGetSymbolAddress((void**)&p_wql,  g_wql);
    cudaGetSymbolAddress((void**)&p_wkh,  g_wkh);
    cudaGetSymbolAddress((void**)&p_wkl,  g_wkl);
    cudaGetSymbolAddress((void**)&p_wvh,  g_wvh);
    cudaGetSymbolAddress((void**)&p_wvl,  g_wvl);
    cudaGetSymbolAddress((void**)&p_woh,  g_woh);
    cudaGetSymbolAddress((void**)&p_wol,  g_wol);
    cudaGetSymbolAddress((void**)&p_xinh, g_xinh);
    cudaGetSymbolAddress((void**)&p_midh, g_midh);
    cudaGetSymbolAddress((void**)&p_w1h,  g_w1h);
    cudaGetSymbolAddress((void**)&p_w2h,  g_w2h);

    // opt-in smem for attention (idempotent; not a stream op)
    cudaFuncSetAttribute(tc_attn, cudaFuncAttributeMaxDynamicSharedMemorySize, TCATTN_SMEM);

    // ---- weight prep: streaming converts ----
    long nproj4 = (long)CD*CD/4;
    convert_kernel<true ><<<1024, 256>>>(Wq, p_wqh, p_wql, nproj4, WSCALE);
    convert_kernel<true ><<<1024, 256>>>(Wk, p_wkh, p_wkl, nproj4, WSCALE);
    convert_kernel<true ><<<1024, 256>>>(Wv, p_wvh, p_wvl, nproj4, WSCALE);
    convert_kernel<true ><<<1024, 256>>>(Wo, p_woh, p_wol, nproj4, WSCALE);
    long nff4 = (long)CE*CD*CDFF/4;
    convert_kernel<false><<<8192, 256>>>(ew1, p_w1h, nullptr, nff4, 1.0f);
    convert_kernel<false><<<8192, 256>>>(ew2, p_w2h, nullptr, nff4, 1.0f);

    // 1. RMSNorm 0 -> split fp16
    rmsnorm_kernel<1><<<CBN, 256>>>(hid, ln0, nullptr, p_nh, p_nl);

    // 2. Q/K/V projections -> split fp16 q/k/v directly
    dim3 gproj(CD/128, CBN/128, 1);
    mma_gemm<3,false,false,2><<<gproj, 256>>>(p_nh, p_nl, p_wqh, p_wql, nullptr, p_qh, p_ql, CD, CD, WISCALE, 0, 0, 0);
    mma_gemm<3,false,false,2><<<gproj, 256>>>(p_nh, p_nl, p_wkh, p_wkl, nullptr, p_kh, p_kl, CD, CD, WISCALE, 0, 0, 0);
    mma_gemm<3,false,false,2><<<gproj, 256>>>(p_nh, p_nl, p_wvh, p_wvl, nullptr, p_vh, p_vl, CD, CD, WISCALE, 0, 0, 0);

    // 3. tensor-core attention -> split fp16 ao
    tc_attn<<<dim3(CN/128, CB*CH), 256, TCATTN_SMEM>>>(mask);

    // 4. output projection + residual -> h (fp32)
    mma_gemm<3,false,true,0><<<gproj, 256>>>(p_aoh, p_aol, p_woh, p_wol, hid, p_h, nullptr, CD, CD, WISCALE, 0, 0, 0);

    // 5. RMSNorm 1 -> fp32
    rmsnorm_kernel<0><<<CBN, 256>>>(p_h, ln1, p_n2, nullptr, nullptr);

    // 6. gating (fp32: routing bit-exact)
    logits_kernel<<<CBN/16, 256>>>(gw);
    gate_kernel<<<(CBN + 255)/256, 256>>>();
    routeinit_kernel<<<(CEC + 255)/256, 256>>>();
    capacity_kernel<<<CB, 32>>>();

    // 7. dispatch (fp16)
    gather_h_kernel<<<CEC, CD/4>>>();

    // 8. expert FFN (fp16 mma, fp32 accum)
    mma_gemm<1,true,false,1><<<dim3(CDFF/128, CMZ/128, CE), 256>>>(
        p_xinh, nullptr, p_w1h, nullptr, nullptr, p_midh, nullptr, CDFF, CD, 1.0f,
        (long)CMZ*CD, (long)CD*CDFF, (long)CMZ*CDFF);
    mma_gemm<1,false,false,0><<<dim3(CD/128, CMZ/128, CE), 256>>>(
        p_midh, nullptr, p_w2h, nullptr, nullptr, p_xo, nullptr, CD, CDFF, 1.0f,
        (long)CMZ*CDFF, (long)CDFF*CD, (long)CMZ*CD);

    // 9. combine + residual 2
    combine_kernel<<<CBN, CD/4>>>(out);

    // 10. aux loss
    loss_kernel<<<1, 128>>>(out, out_size);
}